// round 5
// baseline (speedup 1.0000x reference)
#include <cuda_runtime.h>
#include <cuda_fp16.h>
#include <math.h>

#define SEQ    4096
#define DMODEL 1024
#define HEADS  8
#define ZIPD   256
#define DH     32      // ZIP / HEADS
#define DV     128     // DMODEL / HEADS

// ---------------- scratch (no allocation allowed) ----------------
__device__ __align__(16) float  g_Q[SEQ * ZIPD];          // 4 MB
__device__ __align__(16) float  g_K[SEQ * ZIPD];          // 4 MB
__device__ __align__(16) float  g_T[SEQ * ZIPD];          // 4 MB
__device__ __align__(16) __half g_Kh[SEQ * ZIPD];         // 2 MB  fp16 hi of K-proj
__device__ __align__(16) __half g_Kl[SEQ * ZIPD];         // 2 MB  fp16 lo of K-proj
__device__ __align__(16) __half g_Vt[HEADS * DV * SEQ];   // 8 MB  V transposed per head: [h][n][k]

__device__ __forceinline__ unsigned h2u(__half2 h) { return *reinterpret_cast<unsigned*>(&h); }

// ---------------- fp32 GEMM: C[M,N] = A[M,K] @ W[N,K]^T + bias ----------------
#define BKG 16
#define GPAD 132

template <int MODE>
__device__ __forceinline__ void gemm_body(const float* __restrict__ A,
                                          const float* __restrict__ W,
                                          const float* __restrict__ bias,
                                          float* __restrict__ C,
                                          int N, int K)
{
    __shared__ float As[BKG][GPAD];
    __shared__ float Ws[BKG][GPAD];

    const int tid = threadIdx.x;
    const int tx  = tid & 15;
    const int ty  = tid >> 4;
    const int m0  = blockIdx.y * 128;
    const int n0  = blockIdx.x * 128;
    const int lc  = tid & 3;
    const int lr  = tid >> 2;

    float acc[8][8];
#pragma unroll
    for (int i = 0; i < 8; i++)
#pragma unroll
        for (int j = 0; j < 8; j++) acc[i][j] = 0.f;

    for (int k0 = 0; k0 < K; k0 += BKG) {
        float4 a0 = *(const float4*)(A + (size_t)(m0 + lr)      * K + k0 + lc * 4);
        float4 a1 = *(const float4*)(A + (size_t)(m0 + lr + 64) * K + k0 + lc * 4);
        float4 w0 = *(const float4*)(W + (size_t)(n0 + lr)      * K + k0 + lc * 4);
        float4 w1 = *(const float4*)(W + (size_t)(n0 + lr + 64) * K + k0 + lc * 4);

        __syncthreads();
        As[lc * 4 + 0][lr] = a0.x;  As[lc * 4 + 1][lr] = a0.y;
        As[lc * 4 + 2][lr] = a0.z;  As[lc * 4 + 3][lr] = a0.w;
        As[lc * 4 + 0][lr + 64] = a1.x;  As[lc * 4 + 1][lr + 64] = a1.y;
        As[lc * 4 + 2][lr + 64] = a1.z;  As[lc * 4 + 3][lr + 64] = a1.w;
        Ws[lc * 4 + 0][lr] = w0.x;  Ws[lc * 4 + 1][lr] = w0.y;
        Ws[lc * 4 + 2][lr] = w0.z;  Ws[lc * 4 + 3][lr] = w0.w;
        Ws[lc * 4 + 0][lr + 64] = w1.x;  Ws[lc * 4 + 1][lr + 64] = w1.y;
        Ws[lc * 4 + 2][lr + 64] = w1.z;  Ws[lc * 4 + 3][lr + 64] = w1.w;
        __syncthreads();

#pragma unroll
        for (int kk = 0; kk < BKG; kk++) {
            float a[8], b[8];
            float4 t;
            t = *(const float4*)&As[kk][ty * 4];      a[0]=t.x; a[1]=t.y; a[2]=t.z; a[3]=t.w;
            t = *(const float4*)&As[kk][64 + ty * 4]; a[4]=t.x; a[5]=t.y; a[6]=t.z; a[7]=t.w;
            t = *(const float4*)&Ws[kk][tx * 4];      b[0]=t.x; b[1]=t.y; b[2]=t.z; b[3]=t.w;
            t = *(const float4*)&Ws[kk][64 + tx * 4]; b[4]=t.x; b[5]=t.y; b[6]=t.z; b[7]=t.w;
#pragma unroll
            for (int i = 0; i < 8; i++)
#pragma unroll
                for (int j = 0; j < 8; j++)
                    acc[i][j] = fmaf(a[i], b[j], acc[i][j]);
        }
    }

    if (MODE == 0) {
#pragma unroll
        for (int ih = 0; ih < 2; ih++) {
#pragma unroll
            for (int i = 0; i < 4; i++) {
                int row = m0 + ih * 64 + ty * 4 + i;
#pragma unroll
                for (int jh = 0; jh < 2; jh++) {
                    int col = n0 + jh * 64 + tx * 4;
                    float4 o;
                    o.x = acc[ih * 4 + i][jh * 4 + 0] + bias[col + 0];
                    o.y = acc[ih * 4 + i][jh * 4 + 1] + bias[col + 1];
                    o.z = acc[ih * 4 + i][jh * 4 + 2] + bias[col + 2];
                    o.w = acc[ih * 4 + i][jh * 4 + 3] + bias[col + 3];
                    *(float4*)(C + (size_t)row * N + col) = o;
                }
            }
        }
    } else {
        // transposed fp16 epilogue into g_Vt[(h*DV+n)*SEQ + row]
#pragma unroll
        for (int ih = 0; ih < 2; ih++) {
            int row0 = m0 + ih * 64 + ty * 4;
#pragma unroll
            for (int jh = 0; jh < 2; jh++) {
#pragma unroll
                for (int jj = 0; jj < 4; jj++) {
                    int col = n0 + jh * 64 + tx * 4 + jj;
                    float bv = bias[col];
                    float v0 = acc[ih * 4 + 0][jh * 4 + jj] + bv;
                    float v1 = acc[ih * 4 + 1][jh * 4 + jj] + bv;
                    float v2 = acc[ih * 4 + 2][jh * 4 + jj] + bv;
                    float v3 = acc[ih * 4 + 3][jh * 4 + jj] + bv;
                    __half2 p01 = __floats2half2_rn(v0, v1);
                    __half2 p23 = __floats2half2_rn(v2, v3);
                    int hh = col >> 7;
                    int nn = col & (DV - 1);
                    size_t idx = ((size_t)(hh * DV + nn)) * SEQ + row0;
                    uint2 u; u.x = h2u(p01); u.y = h2u(p23);
                    *reinterpret_cast<uint2*>(&g_Vt[idx]) = u;
                }
            }
        }
    }
}

__global__ void __launch_bounds__(256, 2)
proj_kernel(const float* __restrict__ q, const float* __restrict__ k,
            const float* __restrict__ v,
            const float* __restrict__ wq, const float* __restrict__ bq,
            const float* __restrict__ wk, const float* __restrict__ bk,
            const float* __restrict__ wvr, const float* __restrict__ bvr)
{
    const float *A, *W, *B;
    float* C;
    if (blockIdx.z == 0)      { A = q; W = wq;  B = bq;  C = g_Q; }
    else if (blockIdx.z == 1) { A = k; W = wk;  B = bk;  C = g_K; }
    else                      { A = v; W = wvr; B = bvr; C = g_T; }
    gemm_body<0>(A, W, B, C, ZIPD, DMODEL);
}

__global__ void __launch_bounds__(256, 2)
vl_kernel(const float* __restrict__ wvl, const float* __restrict__ bvl)
{
    gemm_body<1>(g_T, wvl, bvl, nullptr, DMODEL, ZIPD);
}

__global__ void split_k_kernel()
{
    int i = blockIdx.x * 256 + threadIdx.x;
    float4 v = ((const float4*)g_K)[i];
    __half h0 = __float2half_rn(v.x), h1 = __float2half_rn(v.y);
    __half h2 = __float2half_rn(v.z), h3 = __float2half_rn(v.w);
    __half2 hi01 = __halves2half2(h0, h1);
    __half2 hi23 = __halves2half2(h2, h3);
    __half2 lo01 = __floats2half2_rn(v.x - __half2float(h0), v.y - __half2float(h1));
    __half2 lo23 = __floats2half2_rn(v.z - __half2float(h2), v.w - __half2float(h3));
    uint2 uh; uh.x = h2u(hi01); uh.y = h2u(hi23);
    uint2 ul; ul.x = h2u(lo01); ul.y = h2u(lo23);
    ((uint2*)g_Kh)[i] = uh;
    ((uint2*)g_Kl)[i] = ul;
}

// ---------------- fp16-MMA flash attention (LDSM + cp.async pipeline) ----------------
__device__ __forceinline__ void mma16816(float& c0, float& c1, float& c2, float& c3,
                                         unsigned a0, unsigned a1, unsigned a2, unsigned a3,
                                         unsigned b0, unsigned b1)
{
    asm volatile("mma.sync.aligned.m16n8k16.row.col.f32.f16.f16.f32 "
                 "{%0,%1,%2,%3},{%4,%5,%6,%7},{%8,%9},{%0,%1,%2,%3};"
                 : "+f"(c0), "+f"(c1), "+f"(c2), "+f"(c3)
                 : "r"(a0), "r"(a1), "r"(a2), "r"(a3), "r"(b0), "r"(b1));
}

#define LDSM4(R0, R1, R2, R3, ADDR) \
    asm volatile("ldmatrix.sync.aligned.m8n8.x4.shared.b16 {%0,%1,%2,%3}, [%4];" \
                 : "=r"(R0), "=r"(R1), "=r"(R2), "=r"(R3) : "r"(ADDR))

#define CP16(DST, SRC) \
    asm volatile("cp.async.cg.shared.global [%0], [%1], 16;" :: "r"(DST), "l"(SRC))

#define KSTR 40   // halves: 80 B row stride (5 x 16 B) -> conflict-free LDSM
#define VSTR 72   // halves: 144 B row stride (9 x 16 B) -> conflict-free LDSM

// stage layout (halves): [Kh: 64*KSTR][Kl: 64*KSTR][Vt: 128*VSTR]
#define STG_KL   (64 * KSTR)
#define STG_V    (2 * 64 * KSTR)
#define STG_SIZE (2 * 64 * KSTR + 128 * VSTR)   // 14336 halves = 28672 B
#define NTILE    (SEQ / 64)

__global__ void __launch_bounds__(128, 3)
attn_kernel(float* __restrict__ O)
{
    extern __shared__ __align__(16) __half sm[];

    const int tid  = threadIdx.x;
    const int wid  = tid >> 5;
    const int lane = tid & 31;
    const int grp  = lane >> 2;
    const int t    = lane & 3;
    const int h    = blockIdx.y;
    const int q0   = blockIdx.x * 64;
    const int qr   = q0 + wid * 16;

    const unsigned smem_base = (unsigned)__cvta_generic_to_shared(sm);

    // per-lane LDSM address components (byte offsets)
    const int mi = lane >> 3;
    const int r8 = lane & 7;
    // K tile: matrix mi -> (c = mi>>1, khalf = mi&1); row r8
    const unsigned k_lofs = (unsigned)((r8 * KSTR + (mi >> 1) * 16 + (mi & 1) * 8) * 2);
    // V tile: matrix mi -> (nb2 sub = mi>>1, khalf = mi&1); row r8
    const unsigned v_lofs = (unsigned)((((mi >> 1) * 8 + r8) * VSTR + (mi & 1) * 8) * 2);

    // ---- Q fragments (fp16 hi/lo split), held in registers ----
    unsigned qh[2][4], ql[2][4];
#pragma unroll
    for (int c = 0; c < 2; c++) {
        int cb = h * DH + 16 * c;
        const float* r0p = g_Q + (size_t)(qr + grp) * ZIPD + cb;
        const float* r1p = g_Q + (size_t)(qr + grp + 8) * ZIPD + cb;
        float2 xs[4];
        xs[0] = *(const float2*)(r0p + 2 * t);
        xs[1] = *(const float2*)(r1p + 2 * t);
        xs[2] = *(const float2*)(r0p + 8 + 2 * t);
        xs[3] = *(const float2*)(r1p + 8 + 2 * t);
#pragma unroll
        for (int i = 0; i < 4; i++) {
            __half hx = __float2half_rn(xs[i].x);
            __half hy = __float2half_rn(xs[i].y);
            qh[c][i] = h2u(__halves2half2(hx, hy));
            ql[c][i] = h2u(__floats2half2_rn(xs[i].x - __half2float(hx),
                                             xs[i].y - __half2float(hy)));
        }
    }

    float m0v = -1e30f, m1v = -1e30f, l0 = 0.f, l1 = 0.f;
    float o[16][4];
#pragma unroll
    for (int n = 0; n < 16; n++)
#pragma unroll
        for (int j = 0; j < 4; j++) o[n][j] = 0.f;

    // ---- async tile fill (stage, key offset) ----
    auto fill = [&](int stage, int k0) {
        unsigned sbase = smem_base + (unsigned)(stage * STG_SIZE * 2);
        // K hi/lo: 512 16B chunks
#pragma unroll
        for (int it = 0; it < 4; it++) {
            int c   = it * 128 + tid;
            int arr = c >> 8;
            int cc  = c & 255;
            int key = cc >> 2;
            int ch  = cc & 3;
            const __half* src = (arr ? g_Kl : g_Kh) + (size_t)(k0 + key) * ZIPD + h * DH + ch * 8;
            unsigned dst = sbase + (unsigned)(((arr ? STG_KL : 0) + key * KSTR + ch * 8) * 2);
            CP16(dst, src);
        }
        // V: one 64-half row per thread, 8 chunks
        const __half* vsrc = g_Vt + ((size_t)(h * DV + tid)) * SEQ + k0;
        unsigned vdst = sbase + (unsigned)((STG_V + tid * VSTR) * 2);
#pragma unroll
        for (int j = 0; j < 8; j++)
            CP16(vdst + j * 16, vsrc + j * 8);
    };

    fill(0, 0);
    asm volatile("cp.async.commit_group;");

    for (int kt = 0; kt < NTILE; kt++) {
        const int cur = kt & 1;
        if (kt + 1 < NTILE) {
            fill((kt + 1) & 1, (kt + 1) * 64);
            asm volatile("cp.async.commit_group;");
            asm volatile("cp.async.wait_group 1;");
        } else {
            asm volatile("cp.async.wait_group 0;");
        }
        __syncthreads();

        const unsigned sb   = smem_base + (unsigned)(cur * STG_SIZE * 2);
        const unsigned sbKh = sb;
        const unsigned sbKl = sb + STG_KL * 2;
        const unsigned sbV  = sb + STG_V * 2;

        // ---- S = Q K^T (3-pass fp16 split, fp32 accum) ----
        float sc[8][4];
#pragma unroll
        for (int nb = 0; nb < 8; nb++)
#pragma unroll
            for (int j = 0; j < 4; j++) sc[nb][j] = 0.f;

#pragma unroll
        for (int nb = 0; nb < 8; nb++) {
            unsigned bh[4], bl[4];
            LDSM4(bh[0], bh[1], bh[2], bh[3], sbKh + (unsigned)(nb * 8 * KSTR * 2) + k_lofs);
            LDSM4(bl[0], bl[1], bl[2], bl[3], sbKl + (unsigned)(nb * 8 * KSTR * 2) + k_lofs);
#pragma unroll
            for (int c = 0; c < 2; c++) {
                mma16816(sc[nb][0], sc[nb][1], sc[nb][2], sc[nb][3],
                         qh[c][0], qh[c][1], qh[c][2], qh[c][3], bh[2 * c], bh[2 * c + 1]);
                mma16816(sc[nb][0], sc[nb][1], sc[nb][2], sc[nb][3],
                         qh[c][0], qh[c][1], qh[c][2], qh[c][3], bl[2 * c], bl[2 * c + 1]);
                mma16816(sc[nb][0], sc[nb][1], sc[nb][2], sc[nb][3],
                         ql[c][0], ql[c][1], ql[c][2], ql[c][3], bh[2 * c], bh[2 * c + 1]);
            }
        }

        // ---- online softmax (rows grp / grp+8, stats in regs) ----
        float mx0 = -1e30f, mx1 = -1e30f;
#pragma unroll
        for (int nb = 0; nb < 8; nb++) {
            mx0 = fmaxf(mx0, fmaxf(sc[nb][0], sc[nb][1]));
            mx1 = fmaxf(mx1, fmaxf(sc[nb][2], sc[nb][3]));
        }
        mx0 = fmaxf(mx0, __shfl_xor_sync(0xffffffffu, mx0, 1));
        mx0 = fmaxf(mx0, __shfl_xor_sync(0xffffffffu, mx0, 2));
        mx1 = fmaxf(mx1, __shfl_xor_sync(0xffffffffu, mx1, 1));
        mx1 = fmaxf(mx1, __shfl_xor_sync(0xffffffffu, mx1, 2));

        float mn0 = fmaxf(m0v, mx0), mn1 = fmaxf(m1v, mx1);
        float e0 = __expf(m0v - mn0), e1 = __expf(m1v - mn1);
        m0v = mn0; m1v = mn1;

        float s0 = 0.f, s1 = 0.f;
#pragma unroll
        for (int nb = 0; nb < 8; nb++) {
            sc[nb][0] = __expf(sc[nb][0] - mn0);
            sc[nb][1] = __expf(sc[nb][1] - mn0);
            sc[nb][2] = __expf(sc[nb][2] - mn1);
            sc[nb][3] = __expf(sc[nb][3] - mn1);
            s0 += sc[nb][0] + sc[nb][1];
            s1 += sc[nb][2] + sc[nb][3];
        }
        s0 += __shfl_xor_sync(0xffffffffu, s0, 1);
        s0 += __shfl_xor_sync(0xffffffffu, s0, 2);
        s1 += __shfl_xor_sync(0xffffffffu, s1, 1);
        s1 += __shfl_xor_sync(0xffffffffu, s1, 2);
        l0 = l0 * e0 + s0;
        l1 = l1 * e1 + s1;

#pragma unroll
        for (int n = 0; n < 16; n++) {
            o[n][0] *= e0; o[n][1] *= e0;
            o[n][2] *= e1; o[n][3] *= e1;
        }

        // ---- O += P V ----
#pragma unroll
        for (int j = 0; j < 4; j++) {
            unsigned a0 = h2u(__floats2half2_rn(sc[2 * j][0],     sc[2 * j][1]));
            unsigned a1 = h2u(__floats2half2_rn(sc[2 * j][2],     sc[2 * j][3]));
            unsigned a2 = h2u(__floats2half2_rn(sc[2 * j + 1][0], sc[2 * j + 1][1]));
            unsigned a3 = h2u(__floats2half2_rn(sc[2 * j + 1][2], sc[2 * j + 1][3]));
#pragma unroll
            for (int p = 0; p < 8; p++) {
                unsigned bv[4];
                LDSM4(bv[0], bv[1], bv[2], bv[3],
                      sbV + (unsigned)((p * 16 * VSTR + j * 16) * 2) + v_lofs);
                mma16816(o[2 * p][0], o[2 * p][1], o[2 * p][2], o[2 * p][3],
                         a0, a1, a2, a3, bv[0], bv[1]);
                mma16816(o[2 * p + 1][0], o[2 * p + 1][1], o[2 * p + 1][2], o[2 * p + 1][3],
                         a0, a1, a2, a3, bv[2], bv[3]);
            }
        }
        __syncthreads();
    }

    // ---- epilogue ----
    float inv0 = 1.f / l0, inv1 = 1.f / l1;
    int row0 = qr + grp, row1 = qr + grp + 8;
#pragma unroll
    for (int p = 0; p < 16; p++) {
        int col = h * DV + p * 8 + 2 * t;
        *(float2*)(O + (size_t)row0 * DMODEL + col) = make_float2(o[p][0] * inv0, o[p][1] * inv0);
        *(float2*)(O + (size_t)row1 * DMODEL + col) = make_float2(o[p][2] * inv1, o[p][3] * inv1);
    }
}

// ---------------- launch ----------------
extern "C" void kernel_launch(void* const* d_in, const int* in_sizes, int n_in,
                              void* d_out, int out_size)
{
    const float* q   = (const float*)d_in[0];
    const float* k   = (const float*)d_in[1];
    const float* v   = (const float*)d_in[2];
    const float* wq  = (const float*)d_in[3];
    const float* bq  = (const float*)d_in[4];
    const float* wk  = (const float*)d_in[5];
    const float* bk  = (const float*)d_in[6];
    const float* wvr = (const float*)d_in[7];
    const float* bvr = (const float*)d_in[8];
    const float* wvl = (const float*)d_in[9];
    const float* bvl = (const float*)d_in[10];
    float* out = (float*)d_out;

    dim3 pgrid(ZIPD / 128, SEQ / 128, 3);
    proj_kernel<<<pgrid, 256>>>(q, k, v, wq, bq, wk, bk, wvr, bvr);

    split_k_kernel<<<(SEQ * ZIPD / 4) / 256, 256>>>();

    dim3 vgrid(DMODEL / 128, SEQ / 128, 1);
    vl_kernel<<<vgrid, 256>>>(wvl, bvl);

    const int ATTN_SMEM = 2 * STG_SIZE * (int)sizeof(__half);   // 57344 B
    cudaFuncSetAttribute(attn_kernel, cudaFuncAttributeMaxDynamicSharedMemorySize, ATTN_SMEM);
    attn_kernel<<<dim3(SEQ / 64, HEADS), 128, ATTN_SMEM>>>(out);
}

// round 7
// speedup vs baseline: 1.6054x; 1.6054x over previous
#include <cuda_runtime.h>
#include <cuda_fp16.h>
#include <math.h>

#define SEQ    4096
#define DMODEL 1024
#define HEADS  8
#define ZIPD   256
#define DH     32      // ZIP / HEADS
#define DV     128     // DMODEL / HEADS

// ---------------- scratch (no allocation allowed) ----------------
__device__ __align__(16) float  g_Q[SEQ * ZIPD];          // 4 MB
__device__ __align__(16) float  g_K[SEQ * ZIPD];          // 4 MB
__device__ __align__(16) float  g_T[SEQ * ZIPD];          // 4 MB
__device__ __align__(16) __half g_Kh[SEQ * ZIPD];         // 2 MB  fp16 hi of K-proj
__device__ __align__(16) __half g_Kl[SEQ * ZIPD];         // 2 MB  fp16 lo of K-proj
__device__ __align__(16) __half g_Vt[HEADS * DV * SEQ];   // 8 MB  V transposed per head: [h][n][k]

__device__ __forceinline__ unsigned h2u(__half2 h) { return *reinterpret_cast<unsigned*>(&h); }

// ---------------- fp32 GEMM: C[M,N] = A[M,K] @ W[N,K]^T + bias ----------------
#define BKG 16
#define GPAD 132

template <int MODE>
__device__ __forceinline__ void gemm_body(const float* __restrict__ A,
                                          const float* __restrict__ W,
                                          const float* __restrict__ bias,
                                          float* __restrict__ C,
                                          int N, int K)
{
    __shared__ float As[BKG][GPAD];
    __shared__ float Ws[BKG][GPAD];

    const int tid = threadIdx.x;
    const int tx  = tid & 15;
    const int ty  = tid >> 4;
    const int m0  = blockIdx.y * 128;
    const int n0  = blockIdx.x * 128;
    const int lc  = tid & 3;
    const int lr  = tid >> 2;

    float acc[8][8];
#pragma unroll
    for (int i = 0; i < 8; i++)
#pragma unroll
        for (int j = 0; j < 8; j++) acc[i][j] = 0.f;

    for (int k0 = 0; k0 < K; k0 += BKG) {
        float4 a0 = *(const float4*)(A + (size_t)(m0 + lr)      * K + k0 + lc * 4);
        float4 a1 = *(const float4*)(A + (size_t)(m0 + lr + 64) * K + k0 + lc * 4);
        float4 w0 = *(const float4*)(W + (size_t)(n0 + lr)      * K + k0 + lc * 4);
        float4 w1 = *(const float4*)(W + (size_t)(n0 + lr + 64) * K + k0 + lc * 4);

        __syncthreads();
        As[lc * 4 + 0][lr] = a0.x;  As[lc * 4 + 1][lr] = a0.y;
        As[lc * 4 + 2][lr] = a0.z;  As[lc * 4 + 3][lr] = a0.w;
        As[lc * 4 + 0][lr + 64] = a1.x;  As[lc * 4 + 1][lr + 64] = a1.y;
        As[lc * 4 + 2][lr + 64] = a1.z;  As[lc * 4 + 3][lr + 64] = a1.w;
        Ws[lc * 4 + 0][lr] = w0.x;  Ws[lc * 4 + 1][lr] = w0.y;
        Ws[lc * 4 + 2][lr] = w0.z;  Ws[lc * 4 + 3][lr] = w0.w;
        Ws[lc * 4 + 0][lr + 64] = w1.x;  Ws[lc * 4 + 1][lr + 64] = w1.y;
        Ws[lc * 4 + 2][lr + 64] = w1.z;  Ws[lc * 4 + 3][lr + 64] = w1.w;
        __syncthreads();

#pragma unroll
        for (int kk = 0; kk < BKG; kk++) {
            float a[8], b[8];
            float4 t;
            t = *(const float4*)&As[kk][ty * 4];      a[0]=t.x; a[1]=t.y; a[2]=t.z; a[3]=t.w;
            t = *(const float4*)&As[kk][64 + ty * 4]; a[4]=t.x; a[5]=t.y; a[6]=t.z; a[7]=t.w;
            t = *(const float4*)&Ws[kk][tx * 4];      b[0]=t.x; b[1]=t.y; b[2]=t.z; b[3]=t.w;
            t = *(const float4*)&Ws[kk][64 + tx * 4]; b[4]=t.x; b[5]=t.y; b[6]=t.z; b[7]=t.w;
#pragma unroll
            for (int i = 0; i < 8; i++)
#pragma unroll
                for (int j = 0; j < 8; j++)
                    acc[i][j] = fmaf(a[i], b[j], acc[i][j]);
        }
    }

    if (MODE == 0) {
#pragma unroll
        for (int ih = 0; ih < 2; ih++) {
#pragma unroll
            for (int i = 0; i < 4; i++) {
                int row = m0 + ih * 64 + ty * 4 + i;
#pragma unroll
                for (int jh = 0; jh < 2; jh++) {
                    int col = n0 + jh * 64 + tx * 4;
                    float4 o;
                    o.x = acc[ih * 4 + i][jh * 4 + 0] + bias[col + 0];
                    o.y = acc[ih * 4 + i][jh * 4 + 1] + bias[col + 1];
                    o.z = acc[ih * 4 + i][jh * 4 + 2] + bias[col + 2];
                    o.w = acc[ih * 4 + i][jh * 4 + 3] + bias[col + 3];
                    *(float4*)(C + (size_t)row * N + col) = o;
                }
            }
        }
    } else {
        // transposed fp16 epilogue into g_Vt[(h*DV+n)*SEQ + row]
#pragma unroll
        for (int ih = 0; ih < 2; ih++) {
            int row0 = m0 + ih * 64 + ty * 4;
#pragma unroll
            for (int jh = 0; jh < 2; jh++) {
#pragma unroll
                for (int jj = 0; jj < 4; jj++) {
                    int col = n0 + jh * 64 + tx * 4 + jj;
                    float bv = bias[col];
                    float v0 = acc[ih * 4 + 0][jh * 4 + jj] + bv;
                    float v1 = acc[ih * 4 + 1][jh * 4 + jj] + bv;
                    float v2 = acc[ih * 4 + 2][jh * 4 + jj] + bv;
                    float v3 = acc[ih * 4 + 3][jh * 4 + jj] + bv;
                    __half2 p01 = __floats2half2_rn(v0, v1);
                    __half2 p23 = __floats2half2_rn(v2, v3);
                    int hh = col >> 7;
                    int nn = col & (DV - 1);
                    size_t idx = ((size_t)(hh * DV + nn)) * SEQ + row0;
                    uint2 u; u.x = h2u(p01); u.y = h2u(p23);
                    *reinterpret_cast<uint2*>(&g_Vt[idx]) = u;
                }
            }
        }
    }
}

__global__ void __launch_bounds__(256, 2)
proj_kernel(const float* __restrict__ q, const float* __restrict__ k,
            const float* __restrict__ v,
            const float* __restrict__ wq, const float* __restrict__ bq,
            const float* __restrict__ wk, const float* __restrict__ bk,
            const float* __restrict__ wvr, const float* __restrict__ bvr)
{
    const float *A, *W, *B;
    float* C;
    if (blockIdx.z == 0)      { A = q; W = wq;  B = bq;  C = g_Q; }
    else if (blockIdx.z == 1) { A = k; W = wk;  B = bk;  C = g_K; }
    else                      { A = v; W = wvr; B = bvr; C = g_T; }
    gemm_body<0>(A, W, B, C, ZIPD, DMODEL);
}

__global__ void __launch_bounds__(256, 2)
vl_kernel(const float* __restrict__ wvl, const float* __restrict__ bvl)
{
    gemm_body<1>(g_T, wvl, bvl, nullptr, DMODEL, ZIPD);
}

__global__ void split_k_kernel()
{
    int i = blockIdx.x * 256 + threadIdx.x;
    float4 v = ((const float4*)g_K)[i];
    __half h0 = __float2half_rn(v.x), h1 = __float2half_rn(v.y);
    __half h2 = __float2half_rn(v.z), h3 = __float2half_rn(v.w);
    __half2 hi01 = __halves2half2(h0, h1);
    __half2 hi23 = __halves2half2(h2, h3);
    __half2 lo01 = __floats2half2_rn(v.x - __half2float(h0), v.y - __half2float(h1));
    __half2 lo23 = __floats2half2_rn(v.z - __half2float(h2), v.w - __half2float(h3));
    uint2 uh; uh.x = h2u(hi01); uh.y = h2u(hi23);
    uint2 ul; ul.x = h2u(lo01); ul.y = h2u(lo23);
    ((uint2*)g_Kh)[i] = uh;
    ((uint2*)g_Kl)[i] = ul;
}

// ---------------- fp16-MMA flash attention (LDSM + 3-stage cp.async ring) ----------------
__device__ __forceinline__ void mma16816(float& c0, float& c1, float& c2, float& c3,
                                         unsigned a0, unsigned a1, unsigned a2, unsigned a3,
                                         unsigned b0, unsigned b1)
{
    asm volatile("mma.sync.aligned.m16n8k16.row.col.f32.f16.f16.f32 "
                 "{%0,%1,%2,%3},{%4,%5,%6,%7},{%8,%9},{%0,%1,%2,%3};"
                 : "+f"(c0), "+f"(c1), "+f"(c2), "+f"(c3)
                 : "r"(a0), "r"(a1), "r"(a2), "r"(a3), "r"(b0), "r"(b1));
}

#define LDSM4(R0, R1, R2, R3, ADDR) \
    asm volatile("ldmatrix.sync.aligned.m8n8.x4.shared.b16 {%0,%1,%2,%3}, [%4];" \
                 : "=r"(R0), "=r"(R1), "=r"(R2), "=r"(R3) : "r"(ADDR))

#define CP16(DST, SRC) \
    asm volatile("cp.async.cg.shared.global [%0], [%1], 16;" :: "r"(DST), "l"(SRC))

#define KSTR 40   // halves: 80 B row stride (5 x 16 B) -> conflict-free LDSM
#define VSTR 72   // halves: 144 B row stride (9 x 16 B) -> conflict-free LDSM

// stage layout (halves): [Kh: 64*KSTR][Kl: 64*KSTR][Vt: 128*VSTR]
#define STG_KL   (64 * KSTR)
#define STG_V    (2 * 64 * KSTR)
#define STG_SIZE (2 * 64 * KSTR + 128 * VSTR)   // 14336 halves = 28672 B
#define NSTAGE   3
#define NTILE    (SEQ / 64)

__global__ void __launch_bounds__(128, 2)
attn_kernel(float* __restrict__ O)
{
    extern __shared__ __align__(16) __half sm[];

    const int tid  = threadIdx.x;
    const int wid  = tid >> 5;
    const int lane = tid & 31;
    const int grp  = lane >> 2;
    const int t    = lane & 3;
    const int h    = blockIdx.y;
    const int q0   = blockIdx.x * 64;
    const int qr   = q0 + wid * 16;

    const unsigned smem_base = (unsigned)__cvta_generic_to_shared(sm);

    // per-lane LDSM address components (byte offsets)
    const int mi = lane >> 3;
    const int r8 = lane & 7;
    const unsigned k_lofs = (unsigned)((r8 * KSTR + (mi >> 1) * 16 + (mi & 1) * 8) * 2);
    const unsigned v_lofs = (unsigned)((((mi >> 1) * 8 + r8) * VSTR + (mi & 1) * 8) * 2);

    // ---- Q fragments (fp16 hi/lo split), held in registers ----
    unsigned qh[2][4], ql[2][4];
#pragma unroll
    for (int c = 0; c < 2; c++) {
        int cb = h * DH + 16 * c;
        const float* r0p = g_Q + (size_t)(qr + grp) * ZIPD + cb;
        const float* r1p = g_Q + (size_t)(qr + grp + 8) * ZIPD + cb;
        float2 xs[4];
        xs[0] = *(const float2*)(r0p + 2 * t);
        xs[1] = *(const float2*)(r1p + 2 * t);
        xs[2] = *(const float2*)(r0p + 8 + 2 * t);
        xs[3] = *(const float2*)(r1p + 8 + 2 * t);
#pragma unroll
        for (int i = 0; i < 4; i++) {
            __half hx = __float2half_rn(xs[i].x);
            __half hy = __float2half_rn(xs[i].y);
            qh[c][i] = h2u(__halves2half2(hx, hy));
            ql[c][i] = h2u(__floats2half2_rn(xs[i].x - __half2float(hx),
                                             xs[i].y - __half2float(hy)));
        }
    }

    float m0v = -1e30f, m1v = -1e30f, l0 = 0.f, l1 = 0.f;
    float o[16][4];
#pragma unroll
    for (int n = 0; n < 16; n++)
#pragma unroll
        for (int j = 0; j < 4; j++) o[n][j] = 0.f;

    // ---- async tile fill (stage, key offset) ----
    auto fill = [&](int stage, int k0) {
        unsigned sbase = smem_base + (unsigned)(stage * STG_SIZE * 2);
#pragma unroll
        for (int it = 0; it < 4; it++) {
            int c   = it * 128 + tid;
            int arr = c >> 8;
            int cc  = c & 255;
            int key = cc >> 2;
            int ch  = cc & 3;
            const __half* src = (arr ? g_Kl : g_Kh) + (size_t)(k0 + key) * ZIPD + h * DH + ch * 8;
            unsigned dst = sbase + (unsigned)(((arr ? STG_KL : 0) + key * KSTR + ch * 8) * 2);
            CP16(dst, src);
        }
        const __half* vsrc = g_Vt + ((size_t)(h * DV + tid)) * SEQ + k0;
        unsigned vdst = sbase + (unsigned)((STG_V + tid * VSTR) * 2);
#pragma unroll
        for (int j = 0; j < 8; j++)
            CP16(vdst + j * 16, vsrc + j * 8);
    };

    fill(0, 0);
    asm volatile("cp.async.commit_group;");
    fill(1, 64);
    asm volatile("cp.async.commit_group;");

    for (int kt = 0; kt < NTILE; kt++) {
        const int cur = kt % NSTAGE;

        if (kt + 2 < NTILE) {
            asm volatile("cp.async.wait_group 1;");   // tile kt landed
        } else {
            asm volatile("cp.async.wait_group 0;");   // drain at the tail
        }
        __syncthreads();   // (a) tile kt visible to all; (b) stage (kt+2)%3 reads (done at kt-1) fenced

        if (kt + 2 < NTILE) {
            fill((kt + 2) % NSTAGE, (kt + 2) * 64);
            asm volatile("cp.async.commit_group;");
        }

        const unsigned sb   = smem_base + (unsigned)(cur * STG_SIZE * 2);
        const unsigned sbKh = sb;
        const unsigned sbKl = sb + STG_KL * 2;
        const unsigned sbV  = sb + STG_V * 2;

        // ---- S = Q K^T (3-pass fp16 split, fp32 accum) ----
        float sc[8][4];
#pragma unroll
        for (int nb = 0; nb < 8; nb++)
#pragma unroll
            for (int j = 0; j < 4; j++) sc[nb][j] = 0.f;

#pragma unroll
        for (int nb = 0; nb < 8; nb++) {
            unsigned bh[4], bl[4];
            LDSM4(bh[0], bh[1], bh[2], bh[3], sbKh + (unsigned)(nb * 8 * KSTR * 2) + k_lofs);
            LDSM4(bl[0], bl[1], bl[2], bl[3], sbKl + (unsigned)(nb * 8 * KSTR * 2) + k_lofs);
#pragma unroll
            for (int c = 0; c < 2; c++) {
                mma16816(sc[nb][0], sc[nb][1], sc[nb][2], sc[nb][3],
                         qh[c][0], qh[c][1], qh[c][2], qh[c][3], bh[2 * c], bh[2 * c + 1]);
                mma16816(sc[nb][0], sc[nb][1], sc[nb][2], sc[nb][3],
                         qh[c][0], qh[c][1], qh[c][2], qh[c][3], bl[2 * c], bl[2 * c + 1]);
                mma16816(sc[nb][0], sc[nb][1], sc[nb][2], sc[nb][3],
                         ql[c][0], ql[c][1], ql[c][2], ql[c][3], bh[2 * c], bh[2 * c + 1]);
            }
        }

        // ---- online softmax (rows grp / grp+8, stats in regs) ----
        float mx0 = -1e30f, mx1 = -1e30f;
#pragma unroll
        for (int nb = 0; nb < 8; nb++) {
            mx0 = fmaxf(mx0, fmaxf(sc[nb][0], sc[nb][1]));
            mx1 = fmaxf(mx1, fmaxf(sc[nb][2], sc[nb][3]));
        }
        mx0 = fmaxf(mx0, __shfl_xor_sync(0xffffffffu, mx0, 1));
        mx0 = fmaxf(mx0, __shfl_xor_sync(0xffffffffu, mx0, 2));
        mx1 = fmaxf(mx1, __shfl_xor_sync(0xffffffffu, mx1, 1));
        mx1 = fmaxf(mx1, __shfl_xor_sync(0xffffffffu, mx1, 2));

        float mn0 = fmaxf(m0v, mx0), mn1 = fmaxf(m1v, mx1);
        float e0 = __expf(m0v - mn0), e1 = __expf(m1v - mn1);
        m0v = mn0; m1v = mn1;

        float s0 = 0.f, s1 = 0.f;
#pragma unroll
        for (int nb = 0; nb < 8; nb++) {
            sc[nb][0] = __expf(sc[nb][0] - mn0);
            sc[nb][1] = __expf(sc[nb][1] - mn0);
            sc[nb][2] = __expf(sc[nb][2] - mn1);
            sc[nb][3] = __expf(sc[nb][3] - mn1);
            s0 += sc[nb][0] + sc[nb][1];
            s1 += sc[nb][2] + sc[nb][3];
        }
        s0 += __shfl_xor_sync(0xffffffffu, s0, 1);
        s0 += __shfl_xor_sync(0xffffffffu, s0, 2);
        s1 += __shfl_xor_sync(0xffffffffu, s1, 1);
        s1 += __shfl_xor_sync(0xffffffffu, s1, 2);
        l0 = l0 * e0 + s0;
        l1 = l1 * e1 + s1;

#pragma unroll
        for (int n = 0; n < 16; n++) {
            o[n][0] *= e0; o[n][1] *= e0;
            o[n][2] *= e1; o[n][3] *= e1;
        }

        // ---- O += P V ----
#pragma unroll
        for (int j = 0; j < 4; j++) {
            unsigned a0 = h2u(__floats2half2_rn(sc[2 * j][0],     sc[2 * j][1]));
            unsigned a1 = h2u(__floats2half2_rn(sc[2 * j][2],     sc[2 * j][3]));
            unsigned a2 = h2u(__floats2half2_rn(sc[2 * j + 1][0], sc[2 * j + 1][1]));
            unsigned a3 = h2u(__floats2half2_rn(sc[2 * j + 1][2], sc[2 * j + 1][3]));
#pragma unroll
            for (int p = 0; p < 8; p++) {
                unsigned bv[4];
                LDSM4(bv[0], bv[1], bv[2], bv[3],
                      sbV + (unsigned)((p * 16 * VSTR + j * 16) * 2) + v_lofs);
                mma16816(o[2 * p][0], o[2 * p][1], o[2 * p][2], o[2 * p][3],
                         a0, a1, a2, a3, bv[0], bv[1]);
                mma16816(o[2 * p + 1][0], o[2 * p + 1][1], o[2 * p + 1][2], o[2 * p + 1][3],
                         a0, a1, a2, a3, bv[2], bv[3]);
            }
        }
    }

    // ---- epilogue ----
    float inv0 = 1.f / l0, inv1 = 1.f / l1;
    int row0 = qr + grp, row1 = qr + grp + 8;
#pragma unroll
    for (int p = 0; p < 16; p++) {
        int col = h * DV + p * 8 + 2 * t;
        *(float2*)(O + (size_t)row0 * DMODEL + col) = make_float2(o[p][0] * inv0, o[p][1] * inv0);
        *(float2*)(O + (size_t)row1 * DMODEL + col) = make_float2(o[p][2] * inv1, o[p][3] * inv1);
    }
}

// ---------------- launch ----------------
extern "C" void kernel_launch(void* const* d_in, const int* in_sizes, int n_in,
                              void* d_out, int out_size)
{
    const float* q   = (const float*)d_in[0];
    const float* k   = (const float*)d_in[1];
    const float* v   = (const float*)d_in[2];
    const float* wq  = (const float*)d_in[3];
    const float* bq  = (const float*)d_in[4];
    const float* wk  = (const float*)d_in[5];
    const float* bk  = (const float*)d_in[6];
    const float* wvr = (const float*)d_in[7];
    const float* bvr = (const float*)d_in[8];
    const float* wvl = (const float*)d_in[9];
    const float* bvl = (const float*)d_in[10];
    float* out = (float*)d_out;

    dim3 pgrid(ZIPD / 128, SEQ / 128, 3);
    proj_kernel<<<pgrid, 256>>>(q, k, v, wq, bq, wk, bk, wvr, bvr);

    split_k_kernel<<<(SEQ * ZIPD / 4) / 256, 256>>>();

    dim3 vgrid(DMODEL / 128, SEQ / 128, 1);
    vl_kernel<<<vgrid, 256>>>(wvl, bvl);

    const int ATTN_SMEM = NSTAGE * STG_SIZE * (int)sizeof(__half);   // 86016 B
    cudaFuncSetAttribute(attn_kernel, cudaFuncAttributeMaxDynamicSharedMemorySize, ATTN_SMEM);
    attn_kernel<<<dim3(SEQ / 64, HEADS), 128, ATTN_SMEM>>>(out);
}

// round 8
// speedup vs baseline: 2.7624x; 1.7207x over previous
#include <cuda_runtime.h>
#include <cuda_fp16.h>
#include <math.h>

#define SEQ    4096
#define DMODEL 1024
#define HEADS  8
#define ZIPD   256
#define DH     32      // ZIP / HEADS
#define DV     128     // DMODEL / HEADS

// ---------------- scratch (no allocation allowed) ----------------
__device__ __align__(16) float  g_Q[SEQ * ZIPD];                 // 4 MB   fp32 Q-proj
__device__ __align__(16) __half g_Kh[SEQ * ZIPD];                // 2 MB   K-proj hi
__device__ __align__(16) __half g_Kl[SEQ * ZIPD];                // 2 MB   K-proj lo
__device__ __align__(16) __half g_Th[SEQ * ZIPD];                // 2 MB   T (v@wvr) hi
__device__ __align__(16) __half g_Tl[SEQ * ZIPD];                // 2 MB   T lo
__device__ __align__(16) __half g_V[SEQ * DMODEL];               // 8 MB   value, fp16 row-major
__device__ __align__(16) __half g_Inh[3 * SEQ * DMODEL];         // 24 MB  q,k,v hi
__device__ __align__(16) __half g_Inl[3 * SEQ * DMODEL];         // 24 MB  q,k,v lo
__device__ __align__(16) __half g_Wh[3 * ZIPD * DMODEL];         // 1.5 MB wq,wk,wvr hi
__device__ __align__(16) __half g_Wl[3 * ZIPD * DMODEL];         // 1.5 MB lo
__device__ __align__(16) __half g_WVh[DMODEL * ZIPD];            // 0.5 MB wvl hi
__device__ __align__(16) __half g_WVl[DMODEL * ZIPD];            // 0.5 MB lo

__device__ __forceinline__ unsigned h2u(__half2 h) { return *reinterpret_cast<unsigned*>(&h); }

// split float4 -> hi half4 + lo half4
__device__ __forceinline__ void split4(float4 v, uint2& uh, uint2& ul)
{
    __half h0 = __float2half_rn(v.x), h1 = __float2half_rn(v.y);
    __half h2 = __float2half_rn(v.z), h3 = __float2half_rn(v.w);
    uh.x = h2u(__halves2half2(h0, h1));
    uh.y = h2u(__halves2half2(h2, h3));
    ul.x = h2u(__floats2half2_rn(v.x - __half2float(h0), v.y - __half2float(h1)));
    ul.y = h2u(__floats2half2_rn(v.z - __half2float(h2), v.w - __half2float(h3)));
}

// ---------------- conversion kernels ----------------
__global__ void conv_in_kernel(const float* __restrict__ q,
                               const float* __restrict__ k,
                               const float* __restrict__ v)
{
    const float* src = (blockIdx.z == 0) ? q : (blockIdx.z == 1) ? k : v;
    int i = blockIdx.x * 256 + threadIdx.x;              // float4 index
    float4 x = ((const float4*)src)[i];
    uint2 uh, ul;
    split4(x, uh, ul);
    size_t o = (size_t)blockIdx.z * (SEQ * DMODEL / 4) + i;
    ((uint2*)g_Inh)[o] = uh;
    ((uint2*)g_Inl)[o] = ul;
}

__global__ void conv_w_kernel(const float* __restrict__ wq,
                              const float* __restrict__ wk,
                              const float* __restrict__ wvr,
                              const float* __restrict__ wvl)
{
    int i = blockIdx.x * 256 + threadIdx.x;              // float4 index, 0..262143
    const int WSZ = ZIPD * DMODEL / 4;                   // 65536
    uint2 uh, ul;
    if (i < 3 * WSZ) {
        int m = i / WSZ, off = i % WSZ;
        const float* src = (m == 0) ? wq : (m == 1) ? wk : wvr;
        float4 x = ((const float4*)src)[off];
        split4(x, uh, ul);
        ((uint2*)g_Wh)[i] = uh;
        ((uint2*)g_Wl)[i] = ul;
    } else {
        int off = i - 3 * WSZ;
        float4 x = ((const float4*)wvl)[off];
        split4(x, uh, ul);
        ((uint2*)g_WVh)[off] = uh;
        ((uint2*)g_WVl)[off] = ul;
    }
}

// ---------------- MMA helpers ----------------
__device__ __forceinline__ void mma16816(float& c0, float& c1, float& c2, float& c3,
                                         unsigned a0, unsigned a1, unsigned a2, unsigned a3,
                                         unsigned b0, unsigned b1)
{
    asm volatile("mma.sync.aligned.m16n8k16.row.col.f32.f16.f16.f32 "
                 "{%0,%1,%2,%3},{%4,%5,%6,%7},{%8,%9},{%0,%1,%2,%3};"
                 : "+f"(c0), "+f"(c1), "+f"(c2), "+f"(c3)
                 : "r"(a0), "r"(a1), "r"(a2), "r"(a3), "r"(b0), "r"(b1));
}

#define LDSM4(R0, R1, R2, R3, ADDR) \
    asm volatile("ldmatrix.sync.aligned.m8n8.x4.shared.b16 {%0,%1,%2,%3}, [%4];" \
                 : "=r"(R0), "=r"(R1), "=r"(R2), "=r"(R3) : "r"(ADDR))

#define LDSM4T(R0, R1, R2, R3, ADDR) \
    asm volatile("ldmatrix.sync.aligned.m8n8.x4.trans.shared.b16 {%0,%1,%2,%3}, [%4];" \
                 : "=r"(R0), "=r"(R1), "=r"(R2), "=r"(R3) : "r"(ADDR))

#define CP16(DST, SRC) \
    asm volatile("cp.async.cg.shared.global [%0], [%1], 16;" :: "r"(DST), "l"(SRC))

// ---------------- MMA projection GEMM ----------------
// C[4096, N] = A[4096, K] @ W[N, K]^T + bias, hi/lo fp16 split (hh + hl + lh).
// BM=128, BN=64, BK=32, 128 threads (4 warps stacked in M), 2-stage cp.async.
// smem stage (halves): Ah[128*40] Al[128*40] Wh[64*40] Wl[64*40]
#define GASTR 40
#define G_AL  (128 * GASTR)
#define G_WH  (2 * 128 * GASTR)
#define G_WL  (2 * 128 * GASTR + 64 * GASTR)
#define G_STG (2 * 128 * GASTR + 2 * 64 * GASTR)   // 15360 halves = 30720 B

// mode: 0 -> g_Q fp32 [.,256]; 1 -> g_Kh/g_Kl [.,256]; 2 -> g_Th/g_Tl [.,256]; 3 -> g_V fp16 [.,1024]
__device__ __forceinline__ void gemm_mma_body(const __half* __restrict__ Ah,
                                              const __half* __restrict__ Al,
                                              const __half* __restrict__ Wh,
                                              const __half* __restrict__ Wl,
                                              const float* __restrict__ bias,
                                              int K, int mode)
{
    extern __shared__ __align__(16) __half gsm[];
    const unsigned smem_base = (unsigned)__cvta_generic_to_shared(gsm);

    const int tid  = threadIdx.x;
    const int wid  = tid >> 5;
    const int lane = tid & 31;
    const int grp  = lane >> 2;
    const int t    = lane & 3;
    const int mi   = lane >> 3;
    const int r8   = lane & 7;
    const int m0   = blockIdx.y * 128;
    const int n0   = blockIdx.x * 64;

    const unsigned a_lofs = (unsigned)(((((mi & 1) * 8 + r8) * GASTR) + (mi >> 1) * 8) * 2);
    const unsigned w_lofs = (unsigned)((r8 * GASTR + (mi >> 1) * 16 + (mi & 1) * 8) * 2);

    float o[2][8][4];
#pragma unroll
    for (int mf = 0; mf < 2; mf++)
#pragma unroll
        for (int nf = 0; nf < 8; nf++)
#pragma unroll
            for (int r = 0; r < 4; r++) o[mf][nf][r] = 0.f;

    auto fill = [&](int stage, int k0) {
        unsigned sb = smem_base + (unsigned)(stage * G_STG * 2);
        // A: 1024 16B chunks
#pragma unroll
        for (int it = 0; it < 8; it++) {
            int c = it * 128 + tid;
            int arr = c >> 9, cc = c & 511;
            int row = cc >> 2, ch = cc & 3;
            const __half* src = (arr ? Al : Ah) + (size_t)(m0 + row) * K + k0 + ch * 8;
            unsigned dst = sb + (unsigned)(((arr ? G_AL : 0) + row * GASTR + ch * 8) * 2);
            CP16(dst, src);
        }
        // W: 512 16B chunks
#pragma unroll
        for (int it = 0; it < 4; it++) {
            int c = it * 128 + tid;
            int arr = c >> 8, cc = c & 255;
            int row = cc >> 2, ch = cc & 3;
            const __half* src = (arr ? Wl : Wh) + (size_t)(n0 + row) * K + k0 + ch * 8;
            unsigned dst = sb + (unsigned)(((arr ? G_WL : G_WH) + row * GASTR + ch * 8) * 2);
            CP16(dst, src);
        }
    };

    const int NIT = K / 32;
    fill(0, 0);
    asm volatile("cp.async.commit_group;");

    for (int it2 = 0; it2 < NIT; it2++) {
        asm volatile("cp.async.wait_group 0;");
        __syncthreads();
        if (it2 + 1 < NIT) {
            fill((it2 + 1) & 1, (it2 + 1) * 32);
            asm volatile("cp.async.commit_group;");
        }
        unsigned sb = smem_base + (unsigned)((it2 & 1) * G_STG * 2);

        // load A fragments for both k16 halves, hi and lo
        unsigned ah[2][2][4], al[2][2][4];
#pragma unroll
        for (int mf = 0; mf < 2; mf++)
#pragma unroll
            for (int kk = 0; kk < 2; kk++) {
                unsigned base = (unsigned)(((wid * 32 + mf * 16) * GASTR + kk * 16) * 2);
                LDSM4(ah[mf][kk][0], ah[mf][kk][1], ah[mf][kk][2], ah[mf][kk][3],
                      sb + base + a_lofs);
                LDSM4(al[mf][kk][0], al[mf][kk][1], al[mf][kk][2], al[mf][kk][3],
                      sb + (unsigned)(G_AL * 2) + base + a_lofs);
            }

#pragma unroll
        for (int nf = 0; nf < 8; nf++) {
            unsigned wh[4], wl[4];
            unsigned wbase = (unsigned)((nf * 8 * GASTR) * 2);
            LDSM4(wh[0], wh[1], wh[2], wh[3], sb + (unsigned)(G_WH * 2) + wbase + w_lofs);
            LDSM4(wl[0], wl[1], wl[2], wl[3], sb + (unsigned)(G_WL * 2) + wbase + w_lofs);
#pragma unroll
            for (int mf = 0; mf < 2; mf++)
#pragma unroll
                for (int kk = 0; kk < 2; kk++) {
                    mma16816(o[mf][nf][0], o[mf][nf][1], o[mf][nf][2], o[mf][nf][3],
                             ah[mf][kk][0], ah[mf][kk][1], ah[mf][kk][2], ah[mf][kk][3],
                             wh[2 * kk], wh[2 * kk + 1]);
                    mma16816(o[mf][nf][0], o[mf][nf][1], o[mf][nf][2], o[mf][nf][3],
                             ah[mf][kk][0], ah[mf][kk][1], ah[mf][kk][2], ah[mf][kk][3],
                             wl[2 * kk], wl[2 * kk + 1]);
                    mma16816(o[mf][nf][0], o[mf][nf][1], o[mf][nf][2], o[mf][nf][3],
                             al[mf][kk][0], al[mf][kk][1], al[mf][kk][2], al[mf][kk][3],
                             wh[2 * kk], wh[2 * kk + 1]);
                }
        }
    }

    // ---- epilogue ----
#pragma unroll
    for (int mf = 0; mf < 2; mf++) {
        int row0 = m0 + wid * 32 + mf * 16 + grp;
        int row1 = row0 + 8;
#pragma unroll
        for (int nf = 0; nf < 8; nf++) {
            int col = n0 + nf * 8 + 2 * t;
            float b0 = bias[col], b1 = bias[col + 1];
            float x0 = o[mf][nf][0] + b0, x1 = o[mf][nf][1] + b1;
            float x2 = o[mf][nf][2] + b0, x3 = o[mf][nf][3] + b1;
            if (mode == 0) {
                *(float2*)(g_Q + (size_t)row0 * ZIPD + col) = make_float2(x0, x1);
                *(float2*)(g_Q + (size_t)row1 * ZIPD + col) = make_float2(x2, x3);
            } else if (mode == 3) {
                *(__half2*)(g_V + (size_t)row0 * DMODEL + col) = __floats2half2_rn(x0, x1);
                *(__half2*)(g_V + (size_t)row1 * DMODEL + col) = __floats2half2_rn(x2, x3);
            } else {
                __half* Hh = (mode == 1) ? g_Kh : g_Th;
                __half* Hl = (mode == 1) ? g_Kl : g_Tl;
                __half h0 = __float2half_rn(x0), h1 = __float2half_rn(x1);
                __half h2 = __float2half_rn(x2), h3 = __float2half_rn(x3);
                *(__half2*)(Hh + (size_t)row0 * ZIPD + col) = __halves2half2(h0, h1);
                *(__half2*)(Hh + (size_t)row1 * ZIPD + col) = __halves2half2(h2, h3);
                *(__half2*)(Hl + (size_t)row0 * ZIPD + col) =
                    __floats2half2_rn(x0 - __half2float(h0), x1 - __half2float(h1));
                *(__half2*)(Hl + (size_t)row1 * ZIPD + col) =
                    __floats2half2_rn(x2 - __half2float(h2), x3 - __half2float(h3));
            }
        }
    }
}

__global__ void __launch_bounds__(128, 3)
gemm1_kernel(const float* __restrict__ bq, const float* __restrict__ bk,
             const float* __restrict__ bvr)
{
    int z = blockIdx.z;
    const __half* Ah = g_Inh + (size_t)z * SEQ * DMODEL;
    const __half* Al = g_Inl + (size_t)z * SEQ * DMODEL;
    const __half* Wh = g_Wh + (size_t)z * ZIPD * DMODEL;
    const __half* Wl = g_Wl + (size_t)z * ZIPD * DMODEL;
    const float* bias = (z == 0) ? bq : (z == 1) ? bk : bvr;
    gemm_mma_body(Ah, Al, Wh, Wl, bias, DMODEL, z);   // mode 0/1/2
}

__global__ void __launch_bounds__(128, 3)
gemm2_kernel(const float* __restrict__ bvl)
{
    gemm_mma_body(g_Th, g_Tl, g_WVh, g_WVl, bvl, ZIPD, 3);
}

// ---------------- fp16-MMA flash attention (LDSM + 3-stage cp.async ring) ----------------
#define KSTR 40    // halves: 80 B row stride -> conflict-free LDSM
#define VSTR2 136  // halves: 272 B row stride ([k][n] tile) -> conflict-free trans LDSM

// stage layout (halves): [Kh: 64*KSTR][Kl: 64*KSTR][V: 64*VSTR2]
#define STG_KL   (64 * KSTR)
#define STG_V    (2 * 64 * KSTR)
#define STG_SIZE (2 * 64 * KSTR + 64 * VSTR2)   // 13824 halves = 27648 B
#define NSTAGE   3
#define NTILE    (SEQ / 64)

__global__ void __launch_bounds__(128, 2)
attn_kernel(float* __restrict__ O)
{
    extern __shared__ __align__(16) __half sm[];

    const int tid  = threadIdx.x;
    const int wid  = tid >> 5;
    const int lane = tid & 31;
    const int grp  = lane >> 2;
    const int t    = lane & 3;
    const int h    = blockIdx.y;
    const int q0   = blockIdx.x * 64;
    const int qr   = q0 + wid * 16;

    const unsigned smem_base = (unsigned)__cvta_generic_to_shared(sm);

    const int mi = lane >> 3;
    const int r8 = lane & 7;
    const unsigned k_lofs = (unsigned)((r8 * KSTR + (mi >> 1) * 16 + (mi & 1) * 8) * 2);
    // V [k][n] tile, trans ldmatrix: mats (k0-7,nA)(k8-15,nA)(k0-7,nB)(k8-15,nB)
    const unsigned v_lofs = (unsigned)(((((mi & 1) * 8 + r8) * VSTR2) + (mi >> 1) * 8) * 2);

    // ---- Q fragments (fp16 hi/lo split), held in registers ----
    unsigned qh[2][4], ql[2][4];
#pragma unroll
    for (int c = 0; c < 2; c++) {
        int cb = h * DH + 16 * c;
        const float* r0p = g_Q + (size_t)(qr + grp) * ZIPD + cb;
        const float* r1p = g_Q + (size_t)(qr + grp + 8) * ZIPD + cb;
        float2 xs[4];
        xs[0] = *(const float2*)(r0p + 2 * t);
        xs[1] = *(const float2*)(r1p + 2 * t);
        xs[2] = *(const float2*)(r0p + 8 + 2 * t);
        xs[3] = *(const float2*)(r1p + 8 + 2 * t);
#pragma unroll
        for (int i = 0; i < 4; i++) {
            __half hx = __float2half_rn(xs[i].x);
            __half hy = __float2half_rn(xs[i].y);
            qh[c][i] = h2u(__halves2half2(hx, hy));
            ql[c][i] = h2u(__floats2half2_rn(xs[i].x - __half2float(hx),
                                             xs[i].y - __half2float(hy)));
        }
    }

    float m0v = -1e30f, m1v = -1e30f, l0 = 0.f, l1 = 0.f;
    float o[16][4];
#pragma unroll
    for (int n = 0; n < 16; n++)
#pragma unroll
        for (int j = 0; j < 4; j++) o[n][j] = 0.f;

    auto fill = [&](int stage, int k0) {
        unsigned sbase = smem_base + (unsigned)(stage * STG_SIZE * 2);
        // K hi/lo: 512 chunks
#pragma unroll
        for (int it = 0; it < 4; it++) {
            int c   = it * 128 + tid;
            int arr = c >> 8;
            int cc  = c & 255;
            int key = cc >> 2;
            int ch  = cc & 3;
            const __half* src = (arr ? g_Kl : g_Kh) + (size_t)(k0 + key) * ZIPD + h * DH + ch * 8;
            unsigned dst = sbase + (unsigned)(((arr ? STG_KL : 0) + key * KSTR + ch * 8) * 2);
            CP16(dst, src);
        }
        // V row-major [k][n]: 64 rows x 16 chunks = 1024 chunks
#pragma unroll
        for (int it = 0; it < 8; it++) {
            int c   = it * 128 + tid;
            int row = c >> 4;
            int col = c & 15;
            const __half* src = g_V + (size_t)(k0 + row) * DMODEL + h * DV + col * 8;
            unsigned dst = sbase + (unsigned)((STG_V + row * VSTR2 + col * 8) * 2);
            CP16(dst, src);
        }
    };

    fill(0, 0);
    asm volatile("cp.async.commit_group;");
    fill(1, 64);
    asm volatile("cp.async.commit_group;");

    for (int kt = 0; kt < NTILE; kt++) {
        const int cur = kt % NSTAGE;

        if (kt + 2 < NTILE) {
            asm volatile("cp.async.wait_group 1;");
        } else {
            asm volatile("cp.async.wait_group 0;");
        }
        __syncthreads();

        if (kt + 2 < NTILE) {
            fill((kt + 2) % NSTAGE, (kt + 2) * 64);
            asm volatile("cp.async.commit_group;");
        }

        const unsigned sb   = smem_base + (unsigned)(cur * STG_SIZE * 2);
        const unsigned sbKh = sb;
        const unsigned sbKl = sb + STG_KL * 2;
        const unsigned sbV  = sb + STG_V * 2;

        // ---- S = Q K^T (3-pass fp16 split, fp32 accum) ----
        float sc[8][4];
#pragma unroll
        for (int nb = 0; nb < 8; nb++)
#pragma unroll
            for (int j = 0; j < 4; j++) sc[nb][j] = 0.f;

#pragma unroll
        for (int nb = 0; nb < 8; nb++) {
            unsigned bh[4], bl[4];
            LDSM4(bh[0], bh[1], bh[2], bh[3], sbKh + (unsigned)(nb * 8 * KSTR * 2) + k_lofs);
            LDSM4(bl[0], bl[1], bl[2], bl[3], sbKl + (unsigned)(nb * 8 * KSTR * 2) + k_lofs);
#pragma unroll
            for (int c = 0; c < 2; c++) {
                mma16816(sc[nb][0], sc[nb][1], sc[nb][2], sc[nb][3],
                         qh[c][0], qh[c][1], qh[c][2], qh[c][3], bh[2 * c], bh[2 * c + 1]);
                mma16816(sc[nb][0], sc[nb][1], sc[nb][2], sc[nb][3],
                         qh[c][0], qh[c][1], qh[c][2], qh[c][3], bl[2 * c], bl[2 * c + 1]);
                mma16816(sc[nb][0], sc[nb][1], sc[nb][2], sc[nb][3],
                         ql[c][0], ql[c][1], ql[c][2], ql[c][3], bh[2 * c], bh[2 * c + 1]);
            }
        }

        // ---- online softmax ----
        float mx0 = -1e30f, mx1 = -1e30f;
#pragma unroll
        for (int nb = 0; nb < 8; nb++) {
            mx0 = fmaxf(mx0, fmaxf(sc[nb][0], sc[nb][1]));
            mx1 = fmaxf(mx1, fmaxf(sc[nb][2], sc[nb][3]));
        }
        mx0 = fmaxf(mx0, __shfl_xor_sync(0xffffffffu, mx0, 1));
        mx0 = fmaxf(mx0, __shfl_xor_sync(0xffffffffu, mx0, 2));
        mx1 = fmaxf(mx1, __shfl_xor_sync(0xffffffffu, mx1, 1));
        mx1 = fmaxf(mx1, __shfl_xor_sync(0xffffffffu, mx1, 2));

        float mn0 = fmaxf(m0v, mx0), mn1 = fmaxf(m1v, mx1);
        float e0 = __expf(m0v - mn0), e1 = __expf(m1v - mn1);
        m0v = mn0; m1v = mn1;

        float s0 = 0.f, s1 = 0.f;
#pragma unroll
        for (int nb = 0; nb < 8; nb++) {
            sc[nb][0] = __expf(sc[nb][0] - mn0);
            sc[nb][1] = __expf(sc[nb][1] - mn0);
            sc[nb][2] = __expf(sc[nb][2] - mn1);
            sc[nb][3] = __expf(sc[nb][3] - mn1);
            s0 += sc[nb][0] + sc[nb][1];
            s1 += sc[nb][2] + sc[nb][3];
        }
        s0 += __shfl_xor_sync(0xffffffffu, s0, 1);
        s0 += __shfl_xor_sync(0xffffffffu, s0, 2);
        s1 += __shfl_xor_sync(0xffffffffu, s1, 1);
        s1 += __shfl_xor_sync(0xffffffffu, s1, 2);
        l0 = l0 * e0 + s0;
        l1 = l1 * e1 + s1;

#pragma unroll
        for (int n = 0; n < 16; n++) {
            o[n][0] *= e0; o[n][1] *= e0;
            o[n][2] *= e1; o[n][3] *= e1;
        }

        // ---- O += P V  (V via trans-ldmatrix from [k][n] tile) ----
#pragma unroll
        for (int j = 0; j < 4; j++) {
            unsigned a0 = h2u(__floats2half2_rn(sc[2 * j][0],     sc[2 * j][1]));
            unsigned a1 = h2u(__floats2half2_rn(sc[2 * j][2],     sc[2 * j][3]));
            unsigned a2 = h2u(__floats2half2_rn(sc[2 * j + 1][0], sc[2 * j + 1][1]));
            unsigned a3 = h2u(__floats2half2_rn(sc[2 * j + 1][2], sc[2 * j + 1][3]));
#pragma unroll
            for (int p = 0; p < 8; p++) {
                unsigned bv[4];
                LDSM4T(bv[0], bv[1], bv[2], bv[3],
                       sbV + (unsigned)((j * 16 * VSTR2 + p * 16) * 2) + v_lofs);
                mma16816(o[2 * p][0], o[2 * p][1], o[2 * p][2], o[2 * p][3],
                         a0, a1, a2, a3, bv[0], bv[1]);
                mma16816(o[2 * p + 1][0], o[2 * p + 1][1], o[2 * p + 1][2], o[2 * p + 1][3],
                         a0, a1, a2, a3, bv[2], bv[3]);
            }
        }
    }

    // ---- epilogue ----
    float inv0 = 1.f / l0, inv1 = 1.f / l1;
    int row0 = qr + grp, row1 = qr + grp + 8;
#pragma unroll
    for (int p = 0; p < 16; p++) {
        int col = h * DV + p * 8 + 2 * t;
        *(float2*)(O + (size_t)row0 * DMODEL + col) = make_float2(o[p][0] * inv0, o[p][1] * inv0);
        *(float2*)(O + (size_t)row1 * DMODEL + col) = make_float2(o[p][2] * inv1, o[p][3] * inv1);
    }
}

// ---------------- launch ----------------
extern "C" void kernel_launch(void* const* d_in, const int* in_sizes, int n_in,
                              void* d_out, int out_size)
{
    const float* q   = (const float*)d_in[0];
    const float* k   = (const float*)d_in[1];
    const float* v   = (const float*)d_in[2];
    const float* bq  = (const float*)d_in[4];
    const float* bk  = (const float*)d_in[6];
    const float* bvr = (const float*)d_in[8];
    const float* wq  = (const float*)d_in[3];
    const float* wk  = (const float*)d_in[5];
    const float* wvr = (const float*)d_in[7];
    const float* wvl = (const float*)d_in[9];
    const float* bvl = (const float*)d_in[10];
    float* out = (float*)d_out;

    conv_in_kernel<<<dim3(SEQ * DMODEL / 4 / 256, 1, 3), 256>>>(q, k, v);
    conv_w_kernel<<<(4 * ZIPD * DMODEL / 4) / 256, 256>>>(wq, wk, wvr, wvl);

    const int GEMM_SMEM = 2 * G_STG * (int)sizeof(__half);   // 61440 B
    cudaFuncSetAttribute(gemm1_kernel, cudaFuncAttributeMaxDynamicSharedMemorySize, GEMM_SMEM);
    cudaFuncSetAttribute(gemm2_kernel, cudaFuncAttributeMaxDynamicSharedMemorySize, GEMM_SMEM);

    gemm1_kernel<<<dim3(ZIPD / 64, SEQ / 128, 3), 128, GEMM_SMEM>>>(bq, bk, bvr);
    gemm2_kernel<<<dim3(DMODEL / 64, SEQ / 128, 1), 128, GEMM_SMEM>>>(bvl);

    const int ATTN_SMEM = NSTAGE * STG_SIZE * (int)sizeof(__half);   // 82944 B
    cudaFuncSetAttribute(attn_kernel, cudaFuncAttributeMaxDynamicSharedMemorySize, ATTN_SMEM);
    attn_kernel<<<dim3(SEQ / 64, HEADS), 128, ATTN_SMEM>>>(out);
}

// round 9
// speedup vs baseline: 3.1663x; 1.1462x over previous
#include <cuda_runtime.h>
#include <cuda_fp16.h>
#include <math.h>

#define SEQ    4096
#define DMODEL 1024
#define HEADS  8
#define ZIPD   256
#define DH     32      // ZIP / HEADS
#define DV     128     // DMODEL / HEADS

// ---------------- scratch (no allocation allowed) ----------------
__device__ __align__(16) float  g_Q[SEQ * ZIPD];                 // 4 MB   fp32 Q-proj
__device__ __align__(16) __half g_Kh[SEQ * ZIPD];                // 2 MB   K-proj fp16
__device__ __align__(16) __half g_Th[SEQ * ZIPD];                // 2 MB   T (v@wvr) hi
__device__ __align__(16) __half g_Tl[SEQ * ZIPD];                // 2 MB   T lo
__device__ __align__(16) __half g_V[SEQ * DMODEL];               // 8 MB   value, fp16 row-major
__device__ __align__(16) __half g_Inh[3 * SEQ * DMODEL];         // 24 MB  q,k,v hi
__device__ __align__(16) __half g_Inl[3 * SEQ * DMODEL];         // 24 MB  q,k,v lo
__device__ __align__(16) __half g_Wh[3 * ZIPD * DMODEL];         // 1.5 MB wq,wk,wvr hi
__device__ __align__(16) __half g_Wl[3 * ZIPD * DMODEL];         // 1.5 MB lo
__device__ __align__(16) __half g_WVh[DMODEL * ZIPD];            // 0.5 MB wvl hi
__device__ __align__(16) __half g_WVl[DMODEL * ZIPD];            // 0.5 MB lo

__device__ __forceinline__ unsigned h2u(__half2 h) { return *reinterpret_cast<unsigned*>(&h); }

// split float4 -> hi half4 + lo half4
__device__ __forceinline__ void split4(float4 v, uint2& uh, uint2& ul)
{
    __half h0 = __float2half_rn(v.x), h1 = __float2half_rn(v.y);
    __half h2 = __float2half_rn(v.z), h3 = __float2half_rn(v.w);
    uh.x = h2u(__halves2half2(h0, h1));
    uh.y = h2u(__halves2half2(h2, h3));
    ul.x = h2u(__floats2half2_rn(v.x - __half2float(h0), v.y - __half2float(h1)));
    ul.y = h2u(__floats2half2_rn(v.z - __half2float(h2), v.w - __half2float(h3)));
}

// ---------------- conversion kernels ----------------
__global__ void conv_in_kernel(const float* __restrict__ q,
                               const float* __restrict__ k,
                               const float* __restrict__ v)
{
    const float* src = (blockIdx.z == 0) ? q : (blockIdx.z == 1) ? k : v;
    int i = blockIdx.x * 256 + threadIdx.x;              // float4 index
    float4 x = ((const float4*)src)[i];
    uint2 uh, ul;
    split4(x, uh, ul);
    size_t o = (size_t)blockIdx.z * (SEQ * DMODEL / 4) + i;
    ((uint2*)g_Inh)[o] = uh;
    ((uint2*)g_Inl)[o] = ul;
}

__global__ void conv_w_kernel(const float* __restrict__ wq,
                              const float* __restrict__ wk,
                              const float* __restrict__ wvr,
                              const float* __restrict__ wvl)
{
    int i = blockIdx.x * 256 + threadIdx.x;              // float4 index
    const int WSZ = ZIPD * DMODEL / 4;                   // 65536
    uint2 uh, ul;
    if (i < 3 * WSZ) {
        int m = i / WSZ, off = i % WSZ;
        const float* src = (m == 0) ? wq : (m == 1) ? wk : wvr;
        float4 x = ((const float4*)src)[off];
        split4(x, uh, ul);
        ((uint2*)g_Wh)[i] = uh;
        ((uint2*)g_Wl)[i] = ul;
    } else {
        int off = i - 3 * WSZ;
        float4 x = ((const float4*)wvl)[off];
        split4(x, uh, ul);
        ((uint2*)g_WVh)[off] = uh;
        ((uint2*)g_WVl)[off] = ul;
    }
}

// ---------------- MMA helpers ----------------
__device__ __forceinline__ void mma16816(float& c0, float& c1, float& c2, float& c3,
                                         unsigned a0, unsigned a1, unsigned a2, unsigned a3,
                                         unsigned b0, unsigned b1)
{
    asm volatile("mma.sync.aligned.m16n8k16.row.col.f32.f16.f16.f32 "
                 "{%0,%1,%2,%3},{%4,%5,%6,%7},{%8,%9},{%0,%1,%2,%3};"
                 : "+f"(c0), "+f"(c1), "+f"(c2), "+f"(c3)
                 : "r"(a0), "r"(a1), "r"(a2), "r"(a3), "r"(b0), "r"(b1));
}

#define LDSM4(R0, R1, R2, R3, ADDR) \
    asm volatile("ldmatrix.sync.aligned.m8n8.x4.shared.b16 {%0,%1,%2,%3}, [%4];" \
                 : "=r"(R0), "=r"(R1), "=r"(R2), "=r"(R3) : "r"(ADDR))

#define LDSM4T(R0, R1, R2, R3, ADDR) \
    asm volatile("ldmatrix.sync.aligned.m8n8.x4.trans.shared.b16 {%0,%1,%2,%3}, [%4];" \
                 : "=r"(R0), "=r"(R1), "=r"(R2), "=r"(R3) : "r"(ADDR))

#define CP16(DST, SRC) \
    asm volatile("cp.async.cg.shared.global [%0], [%1], 16;" :: "r"(DST), "l"(SRC))

// ---------------- MMA projection GEMM ----------------
// C[4096, N] = A[4096, K] @ W[N, K]^T + bias, hi/lo fp16 split (hh + hl + lh).
#define GASTR 40
#define G_AL  (128 * GASTR)
#define G_WH  (2 * 128 * GASTR)
#define G_WL  (2 * 128 * GASTR + 64 * GASTR)
#define G_STG (2 * 128 * GASTR + 2 * 64 * GASTR)   // 15360 halves = 30720 B

// mode: 0 -> g_Q fp32; 1 -> g_Kh fp16; 2 -> g_Th/g_Tl; 3 -> g_V fp16
__device__ __forceinline__ void gemm_mma_body(const __half* __restrict__ Ah,
                                              const __half* __restrict__ Al,
                                              const __half* __restrict__ Wh,
                                              const __half* __restrict__ Wl,
                                              const float* __restrict__ bias,
                                              int K, int mode)
{
    extern __shared__ __align__(16) __half gsm[];
    const unsigned smem_base = (unsigned)__cvta_generic_to_shared(gsm);

    const int tid  = threadIdx.x;
    const int wid  = tid >> 5;
    const int lane = tid & 31;
    const int grp  = lane >> 2;
    const int t    = lane & 3;
    const int mi   = lane >> 3;
    const int r8   = lane & 7;
    const int m0   = blockIdx.y * 128;
    const int n0   = blockIdx.x * 64;

    const unsigned a_lofs = (unsigned)(((((mi & 1) * 8 + r8) * GASTR) + (mi >> 1) * 8) * 2);
    const unsigned w_lofs = (unsigned)((r8 * GASTR + (mi >> 1) * 16 + (mi & 1) * 8) * 2);

    float o[2][8][4];
#pragma unroll
    for (int mf = 0; mf < 2; mf++)
#pragma unroll
        for (int nf = 0; nf < 8; nf++)
#pragma unroll
            for (int r = 0; r < 4; r++) o[mf][nf][r] = 0.f;

    auto fill = [&](int stage, int k0) {
        unsigned sb = smem_base + (unsigned)(stage * G_STG * 2);
#pragma unroll
        for (int it = 0; it < 8; it++) {
            int c = it * 128 + tid;
            int arr = c >> 9, cc = c & 511;
            int row = cc >> 2, ch = cc & 3;
            const __half* src = (arr ? Al : Ah) + (size_t)(m0 + row) * K + k0 + ch * 8;
            unsigned dst = sb + (unsigned)(((arr ? G_AL : 0) + row * GASTR + ch * 8) * 2);
            CP16(dst, src);
        }
#pragma unroll
        for (int it = 0; it < 4; it++) {
            int c = it * 128 + tid;
            int arr = c >> 8, cc = c & 255;
            int row = cc >> 2, ch = cc & 3;
            const __half* src = (arr ? Wl : Wh) + (size_t)(n0 + row) * K + k0 + ch * 8;
            unsigned dst = sb + (unsigned)(((arr ? G_WL : G_WH) + row * GASTR + ch * 8) * 2);
            CP16(dst, src);
        }
    };

    const int NIT = K / 32;
    fill(0, 0);
    asm volatile("cp.async.commit_group;");

    for (int it2 = 0; it2 < NIT; it2++) {
        asm volatile("cp.async.wait_group 0;");
        __syncthreads();
        if (it2 + 1 < NIT) {
            fill((it2 + 1) & 1, (it2 + 1) * 32);
            asm volatile("cp.async.commit_group;");
        }
        unsigned sb = smem_base + (unsigned)((it2 & 1) * G_STG * 2);

        unsigned ah[2][2][4], al[2][2][4];
#pragma unroll
        for (int mf = 0; mf < 2; mf++)
#pragma unroll
            for (int kk = 0; kk < 2; kk++) {
                unsigned base = (unsigned)(((wid * 32 + mf * 16) * GASTR + kk * 16) * 2);
                LDSM4(ah[mf][kk][0], ah[mf][kk][1], ah[mf][kk][2], ah[mf][kk][3],
                      sb + base + a_lofs);
                LDSM4(al[mf][kk][0], al[mf][kk][1], al[mf][kk][2], al[mf][kk][3],
                      sb + (unsigned)(G_AL * 2) + base + a_lofs);
            }

#pragma unroll
        for (int nf = 0; nf < 8; nf++) {
            unsigned wh[4], wl[4];
            unsigned wbase = (unsigned)((nf * 8 * GASTR) * 2);
            LDSM4(wh[0], wh[1], wh[2], wh[3], sb + (unsigned)(G_WH * 2) + wbase + w_lofs);
            LDSM4(wl[0], wl[1], wl[2], wl[3], sb + (unsigned)(G_WL * 2) + wbase + w_lofs);
#pragma unroll
            for (int mf = 0; mf < 2; mf++)
#pragma unroll
                for (int kk = 0; kk < 2; kk++) {
                    mma16816(o[mf][nf][0], o[mf][nf][1], o[mf][nf][2], o[mf][nf][3],
                             ah[mf][kk][0], ah[mf][kk][1], ah[mf][kk][2], ah[mf][kk][3],
                             wh[2 * kk], wh[2 * kk + 1]);
                    mma16816(o[mf][nf][0], o[mf][nf][1], o[mf][nf][2], o[mf][nf][3],
                             ah[mf][kk][0], ah[mf][kk][1], ah[mf][kk][2], ah[mf][kk][3],
                             wl[2 * kk], wl[2 * kk + 1]);
                    mma16816(o[mf][nf][0], o[mf][nf][1], o[mf][nf][2], o[mf][nf][3],
                             al[mf][kk][0], al[mf][kk][1], al[mf][kk][2], al[mf][kk][3],
                             wh[2 * kk], wh[2 * kk + 1]);
                }
        }
    }

    // ---- epilogue ----
#pragma unroll
    for (int mf = 0; mf < 2; mf++) {
        int row0 = m0 + wid * 32 + mf * 16 + grp;
        int row1 = row0 + 8;
#pragma unroll
        for (int nf = 0; nf < 8; nf++) {
            int col = n0 + nf * 8 + 2 * t;
            float b0 = bias[col], b1 = bias[col + 1];
            float x0 = o[mf][nf][0] + b0, x1 = o[mf][nf][1] + b1;
            float x2 = o[mf][nf][2] + b0, x3 = o[mf][nf][3] + b1;
            if (mode == 0) {
                *(float2*)(g_Q + (size_t)row0 * ZIPD + col) = make_float2(x0, x1);
                *(float2*)(g_Q + (size_t)row1 * ZIPD + col) = make_float2(x2, x3);
            } else if (mode == 1) {
                *(__half2*)(g_Kh + (size_t)row0 * ZIPD + col) = __floats2half2_rn(x0, x1);
                *(__half2*)(g_Kh + (size_t)row1 * ZIPD + col) = __floats2half2_rn(x2, x3);
            } else if (mode == 3) {
                *(__half2*)(g_V + (size_t)row0 * DMODEL + col) = __floats2half2_rn(x0, x1);
                *(__half2*)(g_V + (size_t)row1 * DMODEL + col) = __floats2half2_rn(x2, x3);
            } else {
                __half h0 = __float2half_rn(x0), h1 = __float2half_rn(x1);
                __half h2 = __float2half_rn(x2), h3 = __float2half_rn(x3);
                *(__half2*)(g_Th + (size_t)row0 * ZIPD + col) = __halves2half2(h0, h1);
                *(__half2*)(g_Th + (size_t)row1 * ZIPD + col) = __halves2half2(h2, h3);
                *(__half2*)(g_Tl + (size_t)row0 * ZIPD + col) =
                    __floats2half2_rn(x0 - __half2float(h0), x1 - __half2float(h1));
                *(__half2*)(g_Tl + (size_t)row1 * ZIPD + col) =
                    __floats2half2_rn(x2 - __half2float(h2), x3 - __half2float(h3));
            }
        }
    }
}

__global__ void __launch_bounds__(128, 3)
gemm1_kernel(const float* __restrict__ bq, const float* __restrict__ bk,
             const float* __restrict__ bvr)
{
    int z = blockIdx.z;
    const __half* Ah = g_Inh + (size_t)z * SEQ * DMODEL;
    const __half* Al = g_Inl + (size_t)z * SEQ * DMODEL;
    const __half* Wh = g_Wh + (size_t)z * ZIPD * DMODEL;
    const __half* Wl = g_Wl + (size_t)z * ZIPD * DMODEL;
    const float* bias = (z == 0) ? bq : (z == 1) ? bk : bvr;
    gemm_mma_body(Ah, Al, Wh, Wl, bias, DMODEL, z);   // mode 0/1/2
}

// (128,2): grid 512 at 2/SM -> 1.73 waves @86% vs (128,3)'s 1.15 waves @58%
__global__ void __launch_bounds__(128, 2)
gemm2_kernel(const float* __restrict__ bvl)
{
    gemm_mma_body(g_Th, g_Tl, g_WVh, g_WVl, bvl, ZIPD, 3);
}

// ---------------- fp16-MMA flash attention (single-pass QK, LDSM + 3-stage ring) ----------------
#define KSTR 40    // halves: 80 B row stride -> conflict-free LDSM
#define VSTR2 136  // halves: 272 B row stride ([k][n] tile) -> conflict-free trans LDSM

// stage layout (halves): [Kh: 64*KSTR][V: 64*VSTR2]
#define STG_V    (64 * KSTR)
#define STG_SIZE (64 * KSTR + 64 * VSTR2)   // 11264 halves = 22528 B
#define NSTAGE   3
#define NTILE    (SEQ / 64)

__global__ void __launch_bounds__(128, 2)
attn_kernel(float* __restrict__ O)
{
    extern __shared__ __align__(16) __half sm[];

    const int tid  = threadIdx.x;
    const int wid  = tid >> 5;
    const int lane = tid & 31;
    const int grp  = lane >> 2;
    const int t    = lane & 3;
    const int h    = blockIdx.y;
    const int q0   = blockIdx.x * 64;
    const int qr   = q0 + wid * 16;

    const unsigned smem_base = (unsigned)__cvta_generic_to_shared(sm);

    const int mi = lane >> 3;
    const int r8 = lane & 7;
    const unsigned k_lofs = (unsigned)((r8 * KSTR + (mi >> 1) * 16 + (mi & 1) * 8) * 2);
    const unsigned v_lofs = (unsigned)(((((mi & 1) * 8 + r8) * VSTR2) + (mi >> 1) * 8) * 2);

    // ---- Q fragments (single-pass fp16) ----
    unsigned qh[2][4];
#pragma unroll
    for (int c = 0; c < 2; c++) {
        int cb = h * DH + 16 * c;
        const float* r0p = g_Q + (size_t)(qr + grp) * ZIPD + cb;
        const float* r1p = g_Q + (size_t)(qr + grp + 8) * ZIPD + cb;
        float2 xs[4];
        xs[0] = *(const float2*)(r0p + 2 * t);
        xs[1] = *(const float2*)(r1p + 2 * t);
        xs[2] = *(const float2*)(r0p + 8 + 2 * t);
        xs[3] = *(const float2*)(r1p + 8 + 2 * t);
#pragma unroll
        for (int i = 0; i < 4; i++)
            qh[c][i] = h2u(__floats2half2_rn(xs[i].x, xs[i].y));
    }

    float m0v = -1e30f, m1v = -1e30f, l0 = 0.f, l1 = 0.f;
    float o[16][4];
#pragma unroll
    for (int n = 0; n < 16; n++)
#pragma unroll
        for (int j = 0; j < 4; j++) o[n][j] = 0.f;

    auto fill = [&](int stage, int k0) {
        unsigned sbase = smem_base + (unsigned)(stage * STG_SIZE * 2);
        // K: 256 16B chunks
#pragma unroll
        for (int it = 0; it < 2; it++) {
            int c   = it * 128 + tid;
            int key = c >> 2;
            int ch  = c & 3;
            const __half* src = g_Kh + (size_t)(k0 + key) * ZIPD + h * DH + ch * 8;
            unsigned dst = sbase + (unsigned)((key * KSTR + ch * 8) * 2);
            CP16(dst, src);
        }
        // V row-major [k][n]: 1024 chunks
#pragma unroll
        for (int it = 0; it < 8; it++) {
            int c   = it * 128 + tid;
            int row = c >> 4;
            int col = c & 15;
            const __half* src = g_V + (size_t)(k0 + row) * DMODEL + h * DV + col * 8;
            unsigned dst = sbase + (unsigned)((STG_V + row * VSTR2 + col * 8) * 2);
            CP16(dst, src);
        }
    };

    fill(0, 0);
    asm volatile("cp.async.commit_group;");
    fill(1, 64);
    asm volatile("cp.async.commit_group;");

    for (int kt = 0; kt < NTILE; kt++) {
        const int cur = kt % NSTAGE;

        if (kt + 2 < NTILE) {
            asm volatile("cp.async.wait_group 1;");
        } else {
            asm volatile("cp.async.wait_group 0;");
        }
        __syncthreads();

        if (kt + 2 < NTILE) {
            fill((kt + 2) % NSTAGE, (kt + 2) * 64);
            asm volatile("cp.async.commit_group;");
        }

        const unsigned sb   = smem_base + (unsigned)(cur * STG_SIZE * 2);
        const unsigned sbKh = sb;
        const unsigned sbV  = sb + STG_V * 2;

        // ---- S = Q K^T (single-pass fp16, fp32 accum) ----
        float sc[8][4];
#pragma unroll
        for (int nb = 0; nb < 8; nb++)
#pragma unroll
            for (int j = 0; j < 4; j++) sc[nb][j] = 0.f;

#pragma unroll
        for (int nb = 0; nb < 8; nb++) {
            unsigned bh[4];
            LDSM4(bh[0], bh[1], bh[2], bh[3], sbKh + (unsigned)(nb * 8 * KSTR * 2) + k_lofs);
#pragma unroll
            for (int c = 0; c < 2; c++)
                mma16816(sc[nb][0], sc[nb][1], sc[nb][2], sc[nb][3],
                         qh[c][0], qh[c][1], qh[c][2], qh[c][3], bh[2 * c], bh[2 * c + 1]);
        }

        // ---- online softmax ----
        float mx0 = -1e30f, mx1 = -1e30f;
#pragma unroll
        for (int nb = 0; nb < 8; nb++) {
            mx0 = fmaxf(mx0, fmaxf(sc[nb][0], sc[nb][1]));
            mx1 = fmaxf(mx1, fmaxf(sc[nb][2], sc[nb][3]));
        }
        mx0 = fmaxf(mx0, __shfl_xor_sync(0xffffffffu, mx0, 1));
        mx0 = fmaxf(mx0, __shfl_xor_sync(0xffffffffu, mx0, 2));
        mx1 = fmaxf(mx1, __shfl_xor_sync(0xffffffffu, mx1, 1));
        mx1 = fmaxf(mx1, __shfl_xor_sync(0xffffffffu, mx1, 2));

        float mn0 = fmaxf(m0v, mx0), mn1 = fmaxf(m1v, mx1);
        float e0 = __expf(m0v - mn0), e1 = __expf(m1v - mn1);
        m0v = mn0; m1v = mn1;

        float s0 = 0.f, s1 = 0.f;
#pragma unroll
        for (int nb = 0; nb < 8; nb++) {
            sc[nb][0] = __expf(sc[nb][0] - mn0);
            sc[nb][1] = __expf(sc[nb][1] - mn0);
            sc[nb][2] = __expf(sc[nb][2] - mn1);
            sc[nb][3] = __expf(sc[nb][3] - mn1);
            s0 += sc[nb][0] + sc[nb][1];
            s1 += sc[nb][2] + sc[nb][3];
        }
        s0 += __shfl_xor_sync(0xffffffffu, s0, 1);
        s0 += __shfl_xor_sync(0xffffffffu, s0, 2);
        s1 += __shfl_xor_sync(0xffffffffu, s1, 1);
        s1 += __shfl_xor_sync(0xffffffffu, s1, 2);
        l0 = l0 * e0 + s0;
        l1 = l1 * e1 + s1;

#pragma unroll
        for (int n = 0; n < 16; n++) {
            o[n][0] *= e0; o[n][1] *= e0;
            o[n][2] *= e1; o[n][3] *= e1;
        }

        // ---- O += P V  (V via trans-ldmatrix from [k][n] tile) ----
#pragma unroll
        for (int j = 0; j < 4; j++) {
            unsigned a0 = h2u(__floats2half2_rn(sc[2 * j][0],     sc[2 * j][1]));
            unsigned a1 = h2u(__floats2half2_rn(sc[2 * j][2],     sc[2 * j][3]));
            unsigned a2 = h2u(__floats2half2_rn(sc[2 * j + 1][0], sc[2 * j + 1][1]));
            unsigned a3 = h2u(__floats2half2_rn(sc[2 * j + 1][2], sc[2 * j + 1][3]));
#pragma unroll
            for (int p = 0; p < 8; p++) {
                unsigned bv[4];
                LDSM4T(bv[0], bv[1], bv[2], bv[3],
                       sbV + (unsigned)((j * 16 * VSTR2 + p * 16) * 2) + v_lofs);
                mma16816(o[2 * p][0], o[2 * p][1], o[2 * p][2], o[2 * p][3],
                         a0, a1, a2, a3, bv[0], bv[1]);
                mma16816(o[2 * p + 1][0], o[2 * p + 1][1], o[2 * p + 1][2], o[2 * p + 1][3],
                         a0, a1, a2, a3, bv[2], bv[3]);
            }
        }
    }

    // ---- epilogue ----
    float inv0 = 1.f / l0, inv1 = 1.f / l1;
    int row0 = qr + grp, row1 = qr + grp + 8;
#pragma unroll
    for (int p = 0; p < 16; p++) {
        int col = h * DV + p * 8 + 2 * t;
        *(float2*)(O + (size_t)row0 * DMODEL + col) = make_float2(o[p][0] * inv0, o[p][1] * inv0);
        *(float2*)(O + (size_t)row1 * DMODEL + col) = make_float2(o[p][2] * inv1, o[p][3] * inv1);
    }
}

// ---------------- launch ----------------
extern "C" void kernel_launch(void* const* d_in, const int* in_sizes, int n_in,
                              void* d_out, int out_size)
{
    const float* q   = (const float*)d_in[0];
    const float* k   = (const float*)d_in[1];
    const float* v   = (const float*)d_in[2];
    const float* wq  = (const float*)d_in[3];
    const float* bq  = (const float*)d_in[4];
    const float* wk  = (const float*)d_in[5];
    const float* bk  = (const float*)d_in[6];
    const float* wvr = (const float*)d_in[7];
    const float* bvr = (const float*)d_in[8];
    const float* wvl = (const float*)d_in[9];
    const float* bvl = (const float*)d_in[10];
    float* out = (float*)d_out;

    conv_in_kernel<<<dim3(SEQ * DMODEL / 4 / 256, 1, 3), 256>>>(q, k, v);
    conv_w_kernel<<<(4 * ZIPD * DMODEL / 4) / 256, 256>>>(wq, wk, wvr, wvl);

    const int GEMM_SMEM = 2 * G_STG * (int)sizeof(__half);   // 61440 B
    cudaFuncSetAttribute(gemm1_kernel, cudaFuncAttributeMaxDynamicSharedMemorySize, GEMM_SMEM);
    cudaFuncSetAttribute(gemm2_kernel, cudaFuncAttributeMaxDynamicSharedMemorySize, GEMM_SMEM);

    gemm1_kernel<<<dim3(ZIPD / 64, SEQ / 128, 3), 128, GEMM_SMEM>>>(bq, bk, bvr);
    gemm2_kernel<<<dim3(DMODEL / 64, SEQ / 128, 1), 128, GEMM_SMEM>>>(bvl);

    const int ATTN_SMEM = NSTAGE * STG_SIZE * (int)sizeof(__half);   // 67584 B
    cudaFuncSetAttribute(attn_kernel, cudaFuncAttributeMaxDynamicSharedMemorySize, ATTN_SMEM);
    attn_kernel<<<dim3(SEQ / 64, HEADS), 128, ATTN_SMEM>>>(out);
}

// round 10
// speedup vs baseline: 3.3069x; 1.0444x over previous
#include <cuda_runtime.h>
#include <cuda_fp16.h>
#include <math.h>

#define SEQ    4096
#define DMODEL 1024
#define HEADS  8
#define ZIPD   256
#define DH     32      // ZIP / HEADS
#define DV     128     // DMODEL / HEADS

// ---------------- scratch (no allocation allowed) ----------------
__device__ __align__(16) float  g_Q[SEQ * ZIPD];                 // 4 MB   fp32 Q-proj
__device__ __align__(16) __half g_Kh[SEQ * ZIPD];                // 2 MB   K-proj fp16
__device__ __align__(16) __half g_Th[SEQ * ZIPD];                // 2 MB   T (v@wvr) hi
__device__ __align__(16) __half g_Tl[SEQ * ZIPD];                // 2 MB   T lo
__device__ __align__(16) __half g_V[SEQ * DMODEL];               // 8 MB   value, fp16 row-major
__device__ __align__(16) __half g_Wh[3 * ZIPD * DMODEL];         // 1.5 MB wq,wk,wvr hi
__device__ __align__(16) __half g_Wl[3 * ZIPD * DMODEL];         // 1.5 MB lo
__device__ __align__(16) __half g_WVh[DMODEL * ZIPD];            // 0.5 MB wvl hi
__device__ __align__(16) __half g_WVl[DMODEL * ZIPD];            // 0.5 MB lo

__device__ __forceinline__ unsigned h2u(__half2 h) { return *reinterpret_cast<unsigned*>(&h); }

// split float4 -> hi half4 + lo half4
__device__ __forceinline__ void split4(float4 v, uint2& uh, uint2& ul)
{
    __half h0 = __float2half_rn(v.x), h1 = __float2half_rn(v.y);
    __half h2 = __float2half_rn(v.z), h3 = __float2half_rn(v.w);
    uh.x = h2u(__halves2half2(h0, h1));
    uh.y = h2u(__halves2half2(h2, h3));
    ul.x = h2u(__floats2half2_rn(v.x - __half2float(h0), v.y - __half2float(h1)));
    ul.y = h2u(__floats2half2_rn(v.z - __half2float(h2), v.w - __half2float(h3)));
}

// ---------------- weight conversion ----------------
__global__ void conv_w_kernel(const float* __restrict__ wq,
                              const float* __restrict__ wk,
                              const float* __restrict__ wvr,
                              const float* __restrict__ wvl)
{
    int i = blockIdx.x * 256 + threadIdx.x;              // float4 index
    const int WSZ = ZIPD * DMODEL / 4;                   // 65536
    uint2 uh, ul;
    if (i < 3 * WSZ) {
        int m = i / WSZ, off = i % WSZ;
        const float* src = (m == 0) ? wq : (m == 1) ? wk : wvr;
        float4 x = ((const float4*)src)[off];
        split4(x, uh, ul);
        ((uint2*)g_Wh)[i] = uh;
        ((uint2*)g_Wl)[i] = ul;
    } else {
        int off = i - 3 * WSZ;
        float4 x = ((const float4*)wvl)[off];
        split4(x, uh, ul);
        ((uint2*)g_WVh)[off] = uh;
        ((uint2*)g_WVl)[off] = ul;
    }
}

// ---------------- MMA helpers ----------------
__device__ __forceinline__ void mma16816(float& c0, float& c1, float& c2, float& c3,
                                         unsigned a0, unsigned a1, unsigned a2, unsigned a3,
                                         unsigned b0, unsigned b1)
{
    asm volatile("mma.sync.aligned.m16n8k16.row.col.f32.f16.f16.f32 "
                 "{%0,%1,%2,%3},{%4,%5,%6,%7},{%8,%9},{%0,%1,%2,%3};"
                 : "+f"(c0), "+f"(c1), "+f"(c2), "+f"(c3)
                 : "r"(a0), "r"(a1), "r"(a2), "r"(a3), "r"(b0), "r"(b1));
}

#define LDSM4(R0, R1, R2, R3, ADDR) \
    asm volatile("ldmatrix.sync.aligned.m8n8.x4.shared.b16 {%0,%1,%2,%3}, [%4];" \
                 : "=r"(R0), "=r"(R1), "=r"(R2), "=r"(R3) : "r"(ADDR))

#define LDSM4T(R0, R1, R2, R3, ADDR) \
    asm volatile("ldmatrix.sync.aligned.m8n8.x4.trans.shared.b16 {%0,%1,%2,%3}, [%4];" \
                 : "=r"(R0), "=r"(R1), "=r"(R2), "=r"(R3) : "r"(ADDR))

#define CP16(DST, SRC) \
    asm volatile("cp.async.cg.shared.global [%0], [%1], 16;" :: "r"(DST), "l"(SRC))

// ---------------- GEMM smem layout ----------------
#define GASTR 40
#define G_AL  (128 * GASTR)
#define G_WH  (2 * 128 * GASTR)
#define G_WL  (2 * 128 * GASTR + 64 * GASTR)
#define G_STG (2 * 128 * GASTR + 2 * 64 * GASTR)   // 15360 halves = 30720 B

// ---------------- gemm1: fused fp32->hi/lo split + MMA ----------------
// C[4096, N=256] = A_fp32[4096, 1024] @ W[256, 1024]^T + bias
// mode: 0 -> g_Q fp32; 1 -> g_Kh fp16; 2 -> g_Th/g_Tl
__global__ void __launch_bounds__(128, 3)
gemm1_kernel(const float* __restrict__ qin, const float* __restrict__ kin,
             const float* __restrict__ vin,
             const float* __restrict__ bq, const float* __restrict__ bk,
             const float* __restrict__ bvr)
{
    extern __shared__ __align__(16) __half gsm[];
    const unsigned smem_base = (unsigned)__cvta_generic_to_shared(gsm);

    const int mode = blockIdx.z;
    const float* A    = (mode == 0) ? qin : (mode == 1) ? kin : vin;
    const __half* Wh  = g_Wh + (size_t)mode * ZIPD * DMODEL;
    const __half* Wl  = g_Wl + (size_t)mode * ZIPD * DMODEL;
    const float* bias = (mode == 0) ? bq : (mode == 1) ? bk : bvr;
    const int K = DMODEL;

    const int tid  = threadIdx.x;
    const int wid  = tid >> 5;
    const int lane = tid & 31;
    const int grp  = lane >> 2;
    const int t    = lane & 3;
    const int mi   = lane >> 3;
    const int r8   = lane & 7;
    const int m0   = blockIdx.y * 128;
    const int n0   = blockIdx.x * 64;

    const unsigned a_lofs = (unsigned)(((((mi & 1) * 8 + r8) * GASTR) + (mi >> 1) * 8) * 2);
    const unsigned w_lofs = (unsigned)((r8 * GASTR + (mi >> 1) * 16 + (mi & 1) * 8) * 2);

    float o[2][8][4];
#pragma unroll
    for (int mf = 0; mf < 2; mf++)
#pragma unroll
        for (int nf = 0; nf < 8; nf++)
#pragma unroll
            for (int r = 0; r < 4; r++) o[mf][nf][r] = 0.f;

    float4 areg[8];
    auto ldA = [&](int k0) {
#pragma unroll
        for (int it = 0; it < 8; it++) {
            int c = it * 128 + tid;
            int row = c >> 3, ch = c & 7;
            areg[it] = *(const float4*)(A + (size_t)(m0 + row) * K + k0 + ch * 4);
        }
    };
    auto stsA = [&](int stage) {
#pragma unroll
        for (int it = 0; it < 8; it++) {
            int c = it * 128 + tid;
            int row = c >> 3, ch = c & 7;
            uint2 uh, ul;
            split4(areg[it], uh, ul);
            *(uint2*)(gsm + stage * G_STG + row * GASTR + ch * 4) = uh;
            *(uint2*)(gsm + stage * G_STG + G_AL + row * GASTR + ch * 4) = ul;
        }
    };
    auto fillW = [&](int stage, int k0) {
#pragma unroll
        for (int it = 0; it < 4; it++) {
            int c = it * 128 + tid;
            int arr = c >> 8, cc = c & 255;
            int row = cc >> 2, ch = cc & 3;
            const __half* src = (arr ? Wl : Wh) + (size_t)(n0 + row) * K + k0 + ch * 8;
            unsigned dst = smem_base +
                (unsigned)((stage * G_STG + (arr ? G_WL : G_WH) + row * GASTR + ch * 8) * 2);
            CP16(dst, src);
        }
    };

    const int NIT = K / 32;   // 32
    ldA(0);
    stsA(0);
    fillW(0, 0);
    asm volatile("cp.async.commit_group;");
    ldA(32);   // prefetch next k-block into regs (consumed after this iter's compute)

    for (int it2 = 0; it2 < NIT; it2++) {
        asm volatile("cp.async.wait_group 0;");
        __syncthreads();
        if (it2 + 1 < NIT) {
            stsA((it2 + 1) & 1);                       // stage last read at it2-1; fenced above
            fillW((it2 + 1) & 1, (it2 + 1) * 32);
            asm volatile("cp.async.commit_group;");
            if (it2 + 2 < NIT) ldA((it2 + 2) * 32);
        }
        unsigned sb = smem_base + (unsigned)((it2 & 1) * G_STG * 2);

        unsigned ah[2][2][4], al[2][2][4];
#pragma unroll
        for (int mf = 0; mf < 2; mf++)
#pragma unroll
            for (int kk = 0; kk < 2; kk++) {
                unsigned base = (unsigned)(((wid * 32 + mf * 16) * GASTR + kk * 16) * 2);
                LDSM4(ah[mf][kk][0], ah[mf][kk][1], ah[mf][kk][2], ah[mf][kk][3],
                      sb + base + a_lofs);
                LDSM4(al[mf][kk][0], al[mf][kk][1], al[mf][kk][2], al[mf][kk][3],
                      sb + (unsigned)(G_AL * 2) + base + a_lofs);
            }

#pragma unroll
        for (int nf = 0; nf < 8; nf++) {
            unsigned wh[4], wl[4];
            unsigned wbase = (unsigned)((nf * 8 * GASTR) * 2);
            LDSM4(wh[0], wh[1], wh[2], wh[3], sb + (unsigned)(G_WH * 2) + wbase + w_lofs);
            LDSM4(wl[0], wl[1], wl[2], wl[3], sb + (unsigned)(G_WL * 2) + wbase + w_lofs);
#pragma unroll
            for (int mf = 0; mf < 2; mf++)
#pragma unroll
                for (int kk = 0; kk < 2; kk++) {
                    mma16816(o[mf][nf][0], o[mf][nf][1], o[mf][nf][2], o[mf][nf][3],
                             ah[mf][kk][0], ah[mf][kk][1], ah[mf][kk][2], ah[mf][kk][3],
                             wh[2 * kk], wh[2 * kk + 1]);
                    mma16816(o[mf][nf][0], o[mf][nf][1], o[mf][nf][2], o[mf][nf][3],
                             ah[mf][kk][0], ah[mf][kk][1], ah[mf][kk][2], ah[mf][kk][3],
                             wl[2 * kk], wl[2 * kk + 1]);
                    mma16816(o[mf][nf][0], o[mf][nf][1], o[mf][nf][2], o[mf][nf][3],
                             al[mf][kk][0], al[mf][kk][1], al[mf][kk][2], al[mf][kk][3],
                             wh[2 * kk], wh[2 * kk + 1]);
                }
        }
    }

    // ---- epilogue ----
#pragma unroll
    for (int mf = 0; mf < 2; mf++) {
        int row0 = m0 + wid * 32 + mf * 16 + grp;
        int row1 = row0 + 8;
#pragma unroll
        for (int nf = 0; nf < 8; nf++) {
            int col = n0 + nf * 8 + 2 * t;
            float b0 = bias[col], b1 = bias[col + 1];
            float x0 = o[mf][nf][0] + b0, x1 = o[mf][nf][1] + b1;
            float x2 = o[mf][nf][2] + b0, x3 = o[mf][nf][3] + b1;
            if (mode == 0) {
                *(float2*)(g_Q + (size_t)row0 * ZIPD + col) = make_float2(x0, x1);
                *(float2*)(g_Q + (size_t)row1 * ZIPD + col) = make_float2(x2, x3);
            } else if (mode == 1) {
                *(__half2*)(g_Kh + (size_t)row0 * ZIPD + col) = __floats2half2_rn(x0, x1);
                *(__half2*)(g_Kh + (size_t)row1 * ZIPD + col) = __floats2half2_rn(x2, x3);
            } else {
                __half h0 = __float2half_rn(x0), h1 = __float2half_rn(x1);
                __half h2 = __float2half_rn(x2), h3 = __float2half_rn(x3);
                *(__half2*)(g_Th + (size_t)row0 * ZIPD + col) = __halves2half2(h0, h1);
                *(__half2*)(g_Th + (size_t)row1 * ZIPD + col) = __halves2half2(h2, h3);
                *(__half2*)(g_Tl + (size_t)row0 * ZIPD + col) =
                    __floats2half2_rn(x0 - __half2float(h0), x1 - __half2float(h1));
                *(__half2*)(g_Tl + (size_t)row1 * ZIPD + col) =
                    __floats2half2_rn(x2 - __half2float(h2), x3 - __half2float(h3));
            }
        }
    }
}

// ---------------- gemm2: T @ wvl^T (cp.async A path, 3-pass split) ----------------
__global__ void __launch_bounds__(128, 2)
gemm2_kernel(const float* __restrict__ bvl)
{
    extern __shared__ __align__(16) __half gsm[];
    const unsigned smem_base = (unsigned)__cvta_generic_to_shared(gsm);

    const __half* Ah = g_Th;
    const __half* Al = g_Tl;
    const __half* Wh = g_WVh;
    const __half* Wl = g_WVl;
    const float* bias = bvl;
    const int K = ZIPD;

    const int tid  = threadIdx.x;
    const int wid  = tid >> 5;
    const int lane = tid & 31;
    const int grp  = lane >> 2;
    const int t    = lane & 3;
    const int mi   = lane >> 3;
    const int r8   = lane & 7;
    const int m0   = blockIdx.y * 128;
    const int n0   = blockIdx.x * 64;

    const unsigned a_lofs = (unsigned)(((((mi & 1) * 8 + r8) * GASTR) + (mi >> 1) * 8) * 2);
    const unsigned w_lofs = (unsigned)((r8 * GASTR + (mi >> 1) * 16 + (mi & 1) * 8) * 2);

    float o[2][8][4];
#pragma unroll
    for (int mf = 0; mf < 2; mf++)
#pragma unroll
        for (int nf = 0; nf < 8; nf++)
#pragma unroll
            for (int r = 0; r < 4; r++) o[mf][nf][r] = 0.f;

    auto fill = [&](int stage, int k0) {
        unsigned sb = smem_base + (unsigned)(stage * G_STG * 2);
#pragma unroll
        for (int it = 0; it < 8; it++) {
            int c = it * 128 + tid;
            int arr = c >> 9, cc = c & 511;
            int row = cc >> 2, ch = cc & 3;
            const __half* src = (arr ? Al : Ah) + (size_t)(m0 + row) * K + k0 + ch * 8;
            unsigned dst = sb + (unsigned)(((arr ? G_AL : 0) + row * GASTR + ch * 8) * 2);
            CP16(dst, src);
        }
#pragma unroll
        for (int it = 0; it < 4; it++) {
            int c = it * 128 + tid;
            int arr = c >> 8, cc = c & 255;
            int row = cc >> 2, ch = cc & 3;
            const __half* src = (arr ? Wl : Wh) + (size_t)(n0 + row) * K + k0 + ch * 8;
            unsigned dst = sb + (unsigned)(((arr ? G_WL : G_WH) + row * GASTR + ch * 8) * 2);
            CP16(dst, src);
        }
    };

    const int NIT = K / 32;
    fill(0, 0);
    asm volatile("cp.async.commit_group;");

    for (int it2 = 0; it2 < NIT; it2++) {
        asm volatile("cp.async.wait_group 0;");
        __syncthreads();
        if (it2 + 1 < NIT) {
            fill((it2 + 1) & 1, (it2 + 1) * 32);
            asm volatile("cp.async.commit_group;");
        }
        unsigned sb = smem_base + (unsigned)((it2 & 1) * G_STG * 2);

        unsigned ah[2][2][4], al[2][2][4];
#pragma unroll
        for (int mf = 0; mf < 2; mf++)
#pragma unroll
            for (int kk = 0; kk < 2; kk++) {
                unsigned base = (unsigned)(((wid * 32 + mf * 16) * GASTR + kk * 16) * 2);
                LDSM4(ah[mf][kk][0], ah[mf][kk][1], ah[mf][kk][2], ah[mf][kk][3],
                      sb + base + a_lofs);
                LDSM4(al[mf][kk][0], al[mf][kk][1], al[mf][kk][2], al[mf][kk][3],
                      sb + (unsigned)(G_AL * 2) + base + a_lofs);
            }

#pragma unroll
        for (int nf = 0; nf < 8; nf++) {
            unsigned wh[4], wl[4];
            unsigned wbase = (unsigned)((nf * 8 * GASTR) * 2);
            LDSM4(wh[0], wh[1], wh[2], wh[3], sb + (unsigned)(G_WH * 2) + wbase + w_lofs);
            LDSM4(wl[0], wl[1], wl[2], wl[3], sb + (unsigned)(G_WL * 2) + wbase + w_lofs);
#pragma unroll
            for (int mf = 0; mf < 2; mf++)
#pragma unroll
                for (int kk = 0; kk < 2; kk++) {
                    mma16816(o[mf][nf][0], o[mf][nf][1], o[mf][nf][2], o[mf][nf][3],
                             ah[mf][kk][0], ah[mf][kk][1], ah[mf][kk][2], ah[mf][kk][3],
                             wh[2 * kk], wh[2 * kk + 1]);
                    mma16816(o[mf][nf][0], o[mf][nf][1], o[mf][nf][2], o[mf][nf][3],
                             ah[mf][kk][0], ah[mf][kk][1], ah[mf][kk][2], ah[mf][kk][3],
                             wl[2 * kk], wl[2 * kk + 1]);
                    mma16816(o[mf][nf][0], o[mf][nf][1], o[mf][nf][2], o[mf][nf][3],
                             al[mf][kk][0], al[mf][kk][1], al[mf][kk][2], al[mf][kk][3],
                             wh[2 * kk], wh[2 * kk + 1]);
                }
        }
    }

    // epilogue: fp16 V row-major
#pragma unroll
    for (int mf = 0; mf < 2; mf++) {
        int row0 = m0 + wid * 32 + mf * 16 + grp;
        int row1 = row0 + 8;
#pragma unroll
        for (int nf = 0; nf < 8; nf++) {
            int col = n0 + nf * 8 + 2 * t;
            float b0 = bias[col], b1 = bias[col + 1];
            *(__half2*)(g_V + (size_t)row0 * DMODEL + col) =
                __floats2half2_rn(o[mf][nf][0] + b0, o[mf][nf][1] + b1);
            *(__half2*)(g_V + (size_t)row1 * DMODEL + col) =
                __floats2half2_rn(o[mf][nf][2] + b0, o[mf][nf][3] + b1);
        }
    }
}

// ---------------- fp16-MMA flash attention (single-pass QK, 4-stage ring) ----------------
#define KSTR 40    // halves: 80 B row stride -> conflict-free LDSM
#define VSTR2 136  // halves: 272 B row stride ([k][n] tile) -> conflict-free trans LDSM

#define STG_V    (64 * KSTR)
#define STG_SIZE (64 * KSTR + 64 * VSTR2)   // 11264 halves = 22528 B
#define NSTAGE   4
#define NTILE    (SEQ / 64)

__global__ void __launch_bounds__(128, 2)
attn_kernel(float* __restrict__ O)
{
    extern __shared__ __align__(16) __half sm[];

    const int tid  = threadIdx.x;
    const int wid  = tid >> 5;
    const int lane = tid & 31;
    const int grp  = lane >> 2;
    const int t    = lane & 3;
    const int h    = blockIdx.y;
    const int q0   = blockIdx.x * 64;
    const int qr   = q0 + wid * 16;

    const unsigned smem_base = (unsigned)__cvta_generic_to_shared(sm);

    const int mi = lane >> 3;
    const int r8 = lane & 7;
    const unsigned k_lofs = (unsigned)((r8 * KSTR + (mi >> 1) * 16 + (mi & 1) * 8) * 2);
    const unsigned v_lofs = (unsigned)(((((mi & 1) * 8 + r8) * VSTR2) + (mi >> 1) * 8) * 2);

    // ---- Q fragments (single-pass fp16) ----
    unsigned qh[2][4];
#pragma unroll
    for (int c = 0; c < 2; c++) {
        int cb = h * DH + 16 * c;
        const float* r0p = g_Q + (size_t)(qr + grp) * ZIPD + cb;
        const float* r1p = g_Q + (size_t)(qr + grp + 8) * ZIPD + cb;
        float2 xs[4];
        xs[0] = *(const float2*)(r0p + 2 * t);
        xs[1] = *(const float2*)(r1p + 2 * t);
        xs[2] = *(const float2*)(r0p + 8 + 2 * t);
        xs[3] = *(const float2*)(r1p + 8 + 2 * t);
#pragma unroll
        for (int i = 0; i < 4; i++)
            qh[c][i] = h2u(__floats2half2_rn(xs[i].x, xs[i].y));
    }

    float m0v = -1e30f, m1v = -1e30f, l0 = 0.f, l1 = 0.f;
    float o[16][4];
#pragma unroll
    for (int n = 0; n < 16; n++)
#pragma unroll
        for (int j = 0; j < 4; j++) o[n][j] = 0.f;

    auto fill = [&](int stage, int k0) {
        unsigned sbase = smem_base + (unsigned)(stage * STG_SIZE * 2);
#pragma unroll
        for (int it = 0; it < 2; it++) {
            int c   = it * 128 + tid;
            int key = c >> 2;
            int ch  = c & 3;
            const __half* src = g_Kh + (size_t)(k0 + key) * ZIPD + h * DH + ch * 8;
            unsigned dst = sbase + (unsigned)((key * KSTR + ch * 8) * 2);
            CP16(dst, src);
        }
#pragma unroll
        for (int it = 0; it < 8; it++) {
            int c   = it * 128 + tid;
            int row = c >> 4;
            int col = c & 15;
            const __half* src = g_V + (size_t)(k0 + row) * DMODEL + h * DV + col * 8;
            unsigned dst = sbase + (unsigned)((STG_V + row * VSTR2 + col * 8) * 2);
            CP16(dst, src);
        }
    };

    fill(0, 0);
    asm volatile("cp.async.commit_group;");
    fill(1, 64);
    asm volatile("cp.async.commit_group;");
    fill(2, 128);
    asm volatile("cp.async.commit_group;");

    for (int kt = 0; kt < NTILE; kt++) {
        const int cur = kt & (NSTAGE - 1);

        // exact outstanding-ahead count so tile kt is guaranteed landed
        int ahead = NTILE - 1 - kt;
        if (ahead >= 2)      asm volatile("cp.async.wait_group 2;");
        else if (ahead == 1) asm volatile("cp.async.wait_group 1;");
        else                 asm volatile("cp.async.wait_group 0;");
        __syncthreads();   // tile kt visible; stage (kt+3)&3 reads (done at kt-1) fenced

        if (kt + 3 < NTILE) {
            fill((kt + 3) & (NSTAGE - 1), (kt + 3) * 64);
            asm volatile("cp.async.commit_group;");
        }

        const unsigned sb   = smem_base + (unsigned)(cur * STG_SIZE * 2);
        const unsigned sbKh = sb;
        const unsigned sbV  = sb + STG_V * 2;

        // ---- S = Q K^T (single-pass fp16, fp32 accum) ----
        float sc[8][4];
#pragma unroll
        for (int nb = 0; nb < 8; nb++)
#pragma unroll
            for (int j = 0; j < 4; j++) sc[nb][j] = 0.f;

#pragma unroll
        for (int nb = 0; nb < 8; nb++) {
            unsigned bh[4];
            LDSM4(bh[0], bh[1], bh[2], bh[3], sbKh + (unsigned)(nb * 8 * KSTR * 2) + k_lofs);
#pragma unroll
            for (int c = 0; c < 2; c++)
                mma16816(sc[nb][0], sc[nb][1], sc[nb][2], sc[nb][3],
                         qh[c][0], qh[c][1], qh[c][2], qh[c][3], bh[2 * c], bh[2 * c + 1]);
        }

        // ---- online softmax ----
        float mx0 = -1e30f, mx1 = -1e30f;
#pragma unroll
        for (int nb = 0; nb < 8; nb++) {
            mx0 = fmaxf(mx0, fmaxf(sc[nb][0], sc[nb][1]));
            mx1 = fmaxf(mx1, fmaxf(sc[nb][2], sc[nb][3]));
        }
        mx0 = fmaxf(mx0, __shfl_xor_sync(0xffffffffu, mx0, 1));
        mx0 = fmaxf(mx0, __shfl_xor_sync(0xffffffffu, mx0, 2));
        mx1 = fmaxf(mx1, __shfl_xor_sync(0xffffffffu, mx1, 1));
        mx1 = fmaxf(mx1, __shfl_xor_sync(0xffffffffu, mx1, 2));

        float mn0 = fmaxf(m0v, mx0), mn1 = fmaxf(m1v, mx1);
        float e0 = __expf(m0v - mn0), e1 = __expf(m1v - mn1);
        m0v = mn0; m1v = mn1;

        float s0 = 0.f, s1 = 0.f;
#pragma unroll
        for (int nb = 0; nb < 8; nb++) {
            sc[nb][0] = __expf(sc[nb][0] - mn0);
            sc[nb][1] = __expf(sc[nb][1] - mn0);
            sc[nb][2] = __expf(sc[nb][2] - mn1);
            sc[nb][3] = __expf(sc[nb][3] - mn1);
            s0 += sc[nb][0] + sc[nb][1];
            s1 += sc[nb][2] + sc[nb][3];
        }
        s0 += __shfl_xor_sync(0xffffffffu, s0, 1);
        s0 += __shfl_xor_sync(0xffffffffu, s0, 2);
        s1 += __shfl_xor_sync(0xffffffffu, s1, 1);
        s1 += __shfl_xor_sync(0xffffffffu, s1, 2);
        l0 = l0 * e0 + s0;
        l1 = l1 * e1 + s1;

#pragma unroll
        for (int n = 0; n < 16; n++) {
            o[n][0] *= e0; o[n][1] *= e0;
            o[n][2] *= e1; o[n][3] *= e1;
        }

        // ---- O += P V  (V via trans-ldmatrix from [k][n] tile) ----
#pragma unroll
        for (int j = 0; j < 4; j++) {
            unsigned a0 = h2u(__floats2half2_rn(sc[2 * j][0],     sc[2 * j][1]));
            unsigned a1 = h2u(__floats2half2_rn(sc[2 * j][2],     sc[2 * j][3]));
            unsigned a2 = h2u(__floats2half2_rn(sc[2 * j + 1][0], sc[2 * j + 1][1]));
            unsigned a3 = h2u(__floats2half2_rn(sc[2 * j + 1][2], sc[2 * j + 1][3]));
#pragma unroll
            for (int p = 0; p < 8; p++) {
                unsigned bv[4];
                LDSM4T(bv[0], bv[1], bv[2], bv[3],
                       sbV + (unsigned)((j * 16 * VSTR2 + p * 16) * 2) + v_lofs);
                mma16816(o[2 * p][0], o[2 * p][1], o[2 * p][2], o[2 * p][3],
                         a0, a1, a2, a3, bv[0], bv[1]);
                mma16816(o[2 * p + 1][0], o[2 * p + 1][1], o[2 * p + 1][2], o[2 * p + 1][3],
                         a0, a1, a2, a3, bv[2], bv[3]);
            }
        }
    }

    // ---- epilogue ----
    float inv0 = 1.f / l0, inv1 = 1.f / l1;
    int row0 = qr + grp, row1 = qr + grp + 8;
#pragma unroll
    for (int p = 0; p < 16; p++) {
        int col = h * DV + p * 8 + 2 * t;
        *(float2*)(O + (size_t)row0 * DMODEL + col) = make_float2(o[p][0] * inv0, o[p][1] * inv0);
        *(float2*)(O + (size_t)row1 * DMODEL + col) = make_float2(o[p][2] * inv1, o[p][3] * inv1);
    }
}

// ---------------- launch ----------------
extern "C" void kernel_launch(void* const* d_in, const int* in_sizes, int n_in,
                              void* d_out, int out_size)
{
    const float* q   = (const float*)d_in[0];
    const float* k   = (const float*)d_in[1];
    const float* v   = (const float*)d_in[2];
    const float* wq  = (const float*)d_in[3];
    const float* bq  = (const float*)d_in[4];
    const float* wk  = (const float*)d_in[5];
    const float* bk  = (const float*)d_in[6];
    const float* wvr = (const float*)d_in[7];
    const float* bvr = (const float*)d_in[8];
    const float* wvl = (const float*)d_in[9];
    const float* bvl = (const float*)d_in[10];
    float* out = (float*)d_out;

    conv_w_kernel<<<(4 * ZIPD * DMODEL / 4) / 256, 256>>>(wq, wk, wvr, wvl);

    const int GEMM_SMEM = 2 * G_STG * (int)sizeof(__half);   // 61440 B
    cudaFuncSetAttribute(gemm1_kernel, cudaFuncAttributeMaxDynamicSharedMemorySize, GEMM_SMEM);
    cudaFuncSetAttribute(gemm2_kernel, cudaFuncAttributeMaxDynamicSharedMemorySize, GEMM_SMEM);

    gemm1_kernel<<<dim3(ZIPD / 64, SEQ / 128, 3), 128, GEMM_SMEM>>>(q, k, v, bq, bk, bvr);
    gemm2_kernel<<<dim3(DMODEL / 64, SEQ / 128, 1), 128, GEMM_SMEM>>>(bvl);

    const int ATTN_SMEM = NSTAGE * STG_SIZE * (int)sizeof(__half);   // 90112 B
    cudaFuncSetAttribute(attn_kernel, cudaFuncAttributeMaxDynamicSharedMemorySize, ATTN_SMEM);
    attn_kernel<<<dim3(SEQ / 64, HEADS), 128, ATTN_SMEM>>>(out);
}

// round 11
// speedup vs baseline: 3.3472x; 1.0122x over previous
#include <cuda_runtime.h>
#include <cuda_fp16.h>
#include <math.h>

#define SEQ    4096
#define DMODEL 1024
#define HEADS  8
#define ZIPD   256
#define DH     32      // ZIP / HEADS
#define DV     128     // DMODEL / HEADS

// ---------------- scratch (no allocation allowed) ----------------
__device__ __align__(16) float  g_Q[SEQ * ZIPD];                 // 4 MB   fp32 Q-proj
__device__ __align__(16) __half g_Kh[SEQ * ZIPD];                // 2 MB   K-proj fp16
__device__ __align__(16) __half g_Th[SEQ * ZIPD];                // 2 MB   T (v@wvr) hi
__device__ __align__(16) __half g_Tl[SEQ * ZIPD];                // 2 MB   T lo
__device__ __align__(16) __half g_V[SEQ * DMODEL];               // 8 MB   value, fp16 row-major
__device__ __align__(16) __half g_Wh[3 * ZIPD * DMODEL];         // 1.5 MB wq,wk,wvr hi
__device__ __align__(16) __half g_Wl[3 * ZIPD * DMODEL];         // 1.5 MB lo
__device__ __align__(16) __half g_WVh[DMODEL * ZIPD];            // 0.5 MB wvl hi
__device__ __align__(16) __half g_WVl[DMODEL * ZIPD];            // 0.5 MB lo

__device__ __forceinline__ unsigned h2u(__half2 h) { return *reinterpret_cast<unsigned*>(&h); }

// split float4 -> hi half4 + lo half4
__device__ __forceinline__ void split4(float4 v, uint2& uh, uint2& ul)
{
    __half h0 = __float2half_rn(v.x), h1 = __float2half_rn(v.y);
    __half h2 = __float2half_rn(v.z), h3 = __float2half_rn(v.w);
    uh.x = h2u(__halves2half2(h0, h1));
    uh.y = h2u(__halves2half2(h2, h3));
    ul.x = h2u(__floats2half2_rn(v.x - __half2float(h0), v.y - __half2float(h1)));
    ul.y = h2u(__floats2half2_rn(v.z - __half2float(h2), v.w - __half2float(h3)));
}

// ---------------- weight conversion ----------------
__global__ void conv_w_kernel(const float* __restrict__ wq,
                              const float* __restrict__ wk,
                              const float* __restrict__ wvr,
                              const float* __restrict__ wvl)
{
    int i = blockIdx.x * 256 + threadIdx.x;              // float4 index
    const int WSZ = ZIPD * DMODEL / 4;                   // 65536
    uint2 uh, ul;
    if (i < 3 * WSZ) {
        int m = i / WSZ, off = i % WSZ;
        const float* src = (m == 0) ? wq : (m == 1) ? wk : wvr;
        float4 x = ((const float4*)src)[off];
        split4(x, uh, ul);
        ((uint2*)g_Wh)[i] = uh;
        ((uint2*)g_Wl)[i] = ul;
    } else {
        int off = i - 3 * WSZ;
        float4 x = ((const float4*)wvl)[off];
        split4(x, uh, ul);
        ((uint2*)g_WVh)[off] = uh;
        ((uint2*)g_WVl)[off] = ul;
    }
}

// ---------------- MMA helpers ----------------
__device__ __forceinline__ void mma16816(float& c0, float& c1, float& c2, float& c3,
                                         unsigned a0, unsigned a1, unsigned a2, unsigned a3,
                                         unsigned b0, unsigned b1)
{
    asm volatile("mma.sync.aligned.m16n8k16.row.col.f32.f16.f16.f32 "
                 "{%0,%1,%2,%3},{%4,%5,%6,%7},{%8,%9},{%0,%1,%2,%3};"
                 : "+f"(c0), "+f"(c1), "+f"(c2), "+f"(c3)
                 : "r"(a0), "r"(a1), "r"(a2), "r"(a3), "r"(b0), "r"(b1));
}

#define LDSM4(R0, R1, R2, R3, ADDR) \
    asm volatile("ldmatrix.sync.aligned.m8n8.x4.shared.b16 {%0,%1,%2,%3}, [%4];" \
                 : "=r"(R0), "=r"(R1), "=r"(R2), "=r"(R3) : "r"(ADDR))

#define LDSM4T(R0, R1, R2, R3, ADDR) \
    asm volatile("ldmatrix.sync.aligned.m8n8.x4.trans.shared.b16 {%0,%1,%2,%3}, [%4];" \
                 : "=r"(R0), "=r"(R1), "=r"(R2), "=r"(R3) : "r"(ADDR))

#define CP16(DST, SRC) \
    asm volatile("cp.async.cg.shared.global [%0], [%1], 16;" :: "r"(DST), "l"(SRC))

// ---------------- GEMM smem layout ----------------
#define GASTR 40
#define G_AL  (128 * GASTR)
#define G_WH  (2 * 128 * GASTR)
#define G_WL  (2 * 128 * GASTR + 64 * GASTR)
#define G_STG (2 * 128 * GASTR + 2 * 64 * GASTR)   // 15360 halves = 30720 B

// ---------------- gemm1: fused fp32->hi/lo split + MMA ----------------
// mode: 0 -> g_Q fp32; 1 -> g_Kh fp16; 2 -> g_Th/g_Tl
__global__ void __launch_bounds__(128, 3)
gemm1_kernel(const float* __restrict__ qin, const float* __restrict__ kin,
             const float* __restrict__ vin,
             const float* __restrict__ bq, const float* __restrict__ bk,
             const float* __restrict__ bvr)
{
    extern __shared__ __align__(16) __half gsm[];
    const unsigned smem_base = (unsigned)__cvta_generic_to_shared(gsm);

    const int mode = blockIdx.z;
    const float* A    = (mode == 0) ? qin : (mode == 1) ? kin : vin;
    const __half* Wh  = g_Wh + (size_t)mode * ZIPD * DMODEL;
    const __half* Wl  = g_Wl + (size_t)mode * ZIPD * DMODEL;
    const float* bias = (mode == 0) ? bq : (mode == 1) ? bk : bvr;
    const int K = DMODEL;

    const int tid  = threadIdx.x;
    const int wid  = tid >> 5;
    const int lane = tid & 31;
    const int grp  = lane >> 2;
    const int t    = lane & 3;
    const int mi   = lane >> 3;
    const int r8   = lane & 7;
    const int m0   = blockIdx.y * 128;
    const int n0   = blockIdx.x * 64;

    const unsigned a_lofs = (unsigned)(((((mi & 1) * 8 + r8) * GASTR) + (mi >> 1) * 8) * 2);
    const unsigned w_lofs = (unsigned)((r8 * GASTR + (mi >> 1) * 16 + (mi & 1) * 8) * 2);

    float o[2][8][4];
#pragma unroll
    for (int mf = 0; mf < 2; mf++)
#pragma unroll
        for (int nf = 0; nf < 8; nf++)
#pragma unroll
            for (int r = 0; r < 4; r++) o[mf][nf][r] = 0.f;

    float4 areg[8];
    auto ldA = [&](int k0) {
#pragma unroll
        for (int it = 0; it < 8; it++) {
            int c = it * 128 + tid;
            int row = c >> 3, ch = c & 7;
            areg[it] = *(const float4*)(A + (size_t)(m0 + row) * K + k0 + ch * 4);
        }
    };
    auto stsA = [&](int stage) {
#pragma unroll
        for (int it = 0; it < 8; it++) {
            int c = it * 128 + tid;
            int row = c >> 3, ch = c & 7;
            uint2 uh, ul;
            split4(areg[it], uh, ul);
            *(uint2*)(gsm + stage * G_STG + row * GASTR + ch * 4) = uh;
            *(uint2*)(gsm + stage * G_STG + G_AL + row * GASTR + ch * 4) = ul;
        }
    };
    auto fillW = [&](int stage, int k0) {
#pragma unroll
        for (int it = 0; it < 4; it++) {
            int c = it * 128 + tid;
            int arr = c >> 8, cc = c & 255;
            int row = cc >> 2, ch = cc & 3;
            const __half* src = (arr ? Wl : Wh) + (size_t)(n0 + row) * K + k0 + ch * 8;
            unsigned dst = smem_base +
                (unsigned)((stage * G_STG + (arr ? G_WL : G_WH) + row * GASTR + ch * 8) * 2);
            CP16(dst, src);
        }
    };

    const int NIT = K / 32;   // 32
    ldA(0);
    stsA(0);
    fillW(0, 0);
    asm volatile("cp.async.commit_group;");
    ldA(32);

    for (int it2 = 0; it2 < NIT; it2++) {
        asm volatile("cp.async.wait_group 0;");
        __syncthreads();
        if (it2 + 1 < NIT) {
            stsA((it2 + 1) & 1);
            fillW((it2 + 1) & 1, (it2 + 1) * 32);
            asm volatile("cp.async.commit_group;");
            if (it2 + 2 < NIT) ldA((it2 + 2) * 32);
        }
        unsigned sb = smem_base + (unsigned)((it2 & 1) * G_STG * 2);

        unsigned ah[2][2][4], al[2][2][4];
#pragma unroll
        for (int mf = 0; mf < 2; mf++)
#pragma unroll
            for (int kk = 0; kk < 2; kk++) {
                unsigned base = (unsigned)(((wid * 32 + mf * 16) * GASTR + kk * 16) * 2);
                LDSM4(ah[mf][kk][0], ah[mf][kk][1], ah[mf][kk][2], ah[mf][kk][3],
                      sb + base + a_lofs);
                LDSM4(al[mf][kk][0], al[mf][kk][1], al[mf][kk][2], al[mf][kk][3],
                      sb + (unsigned)(G_AL * 2) + base + a_lofs);
            }

#pragma unroll
        for (int nf = 0; nf < 8; nf++) {
            unsigned wh[4], wl[4];
            unsigned wbase = (unsigned)((nf * 8 * GASTR) * 2);
            LDSM4(wh[0], wh[1], wh[2], wh[3], sb + (unsigned)(G_WH * 2) + wbase + w_lofs);
            LDSM4(wl[0], wl[1], wl[2], wl[3], sb + (unsigned)(G_WL * 2) + wbase + w_lofs);
#pragma unroll
            for (int mf = 0; mf < 2; mf++)
#pragma unroll
                for (int kk = 0; kk < 2; kk++) {
                    mma16816(o[mf][nf][0], o[mf][nf][1], o[mf][nf][2], o[mf][nf][3],
                             ah[mf][kk][0], ah[mf][kk][1], ah[mf][kk][2], ah[mf][kk][3],
                             wh[2 * kk], wh[2 * kk + 1]);
                    mma16816(o[mf][nf][0], o[mf][nf][1], o[mf][nf][2], o[mf][nf][3],
                             ah[mf][kk][0], ah[mf][kk][1], ah[mf][kk][2], ah[mf][kk][3],
                             wl[2 * kk], wl[2 * kk + 1]);
                    mma16816(o[mf][nf][0], o[mf][nf][1], o[mf][nf][2], o[mf][nf][3],
                             al[mf][kk][0], al[mf][kk][1], al[mf][kk][2], al[mf][kk][3],
                             wh[2 * kk], wh[2 * kk + 1]);
                }
        }
    }

    // ---- epilogue ----
#pragma unroll
    for (int mf = 0; mf < 2; mf++) {
        int row0 = m0 + wid * 32 + mf * 16 + grp;
        int row1 = row0 + 8;
#pragma unroll
        for (int nf = 0; nf < 8; nf++) {
            int col = n0 + nf * 8 + 2 * t;
            float b0 = bias[col], b1 = bias[col + 1];
            float x0 = o[mf][nf][0] + b0, x1 = o[mf][nf][1] + b1;
            float x2 = o[mf][nf][2] + b0, x3 = o[mf][nf][3] + b1;
            if (mode == 0) {
                *(float2*)(g_Q + (size_t)row0 * ZIPD + col) = make_float2(x0, x1);
                *(float2*)(g_Q + (size_t)row1 * ZIPD + col) = make_float2(x2, x3);
            } else if (mode == 1) {
                *(__half2*)(g_Kh + (size_t)row0 * ZIPD + col) = __floats2half2_rn(x0, x1);
                *(__half2*)(g_Kh + (size_t)row1 * ZIPD + col) = __floats2half2_rn(x2, x3);
            } else {
                __half h0 = __float2half_rn(x0), h1 = __float2half_rn(x1);
                __half h2 = __float2half_rn(x2), h3 = __float2half_rn(x3);
                *(__half2*)(g_Th + (size_t)row0 * ZIPD + col) = __halves2half2(h0, h1);
                *(__half2*)(g_Th + (size_t)row1 * ZIPD + col) = __halves2half2(h2, h3);
                *(__half2*)(g_Tl + (size_t)row0 * ZIPD + col) =
                    __floats2half2_rn(x0 - __half2float(h0), x1 - __half2float(h1));
                *(__half2*)(g_Tl + (size_t)row1 * ZIPD + col) =
                    __floats2half2_rn(x2 - __half2float(h2), x3 - __half2float(h3));
            }
        }
    }
}

// ---------------- gemm2: T @ wvl^T ----------------
__global__ void __launch_bounds__(128, 2)
gemm2_kernel(const float* __restrict__ bvl)
{
    extern __shared__ __align__(16) __half gsm[];
    const unsigned smem_base = (unsigned)__cvta_generic_to_shared(gsm);

    const __half* Ah = g_Th;
    const __half* Al = g_Tl;
    const __half* Wh = g_WVh;
    const __half* Wl = g_WVl;
    const float* bias = bvl;
    const int K = ZIPD;

    const int tid  = threadIdx.x;
    const int wid  = tid >> 5;
    const int lane = tid & 31;
    const int grp  = lane >> 2;
    const int t    = lane & 3;
    const int mi   = lane >> 3;
    const int r8   = lane & 7;
    const int m0   = blockIdx.y * 128;
    const int n0   = blockIdx.x * 64;

    const unsigned a_lofs = (unsigned)(((((mi & 1) * 8 + r8) * GASTR) + (mi >> 1) * 8) * 2);
    const unsigned w_lofs = (unsigned)((r8 * GASTR + (mi >> 1) * 16 + (mi & 1) * 8) * 2);

    float o[2][8][4];
#pragma unroll
    for (int mf = 0; mf < 2; mf++)
#pragma unroll
        for (int nf = 0; nf < 8; nf++)
#pragma unroll
            for (int r = 0; r < 4; r++) o[mf][nf][r] = 0.f;

    auto fill = [&](int stage, int k0) {
        unsigned sb = smem_base + (unsigned)(stage * G_STG * 2);
#pragma unroll
        for (int it = 0; it < 8; it++) {
            int c = it * 128 + tid;
            int arr = c >> 9, cc = c & 511;
            int row = cc >> 2, ch = cc & 3;
            const __half* src = (arr ? Al : Ah) + (size_t)(m0 + row) * K + k0 + ch * 8;
            unsigned dst = sb + (unsigned)(((arr ? G_AL : 0) + row * GASTR + ch * 8) * 2);
            CP16(dst, src);
        }
#pragma unroll
        for (int it = 0; it < 4; it++) {
            int c = it * 128 + tid;
            int arr = c >> 8, cc = c & 255;
            int row = cc >> 2, ch = cc & 3;
            const __half* src = (arr ? Wl : Wh) + (size_t)(n0 + row) * K + k0 + ch * 8;
            unsigned dst = sb + (unsigned)(((arr ? G_WL : G_WH) + row * GASTR + ch * 8) * 2);
            CP16(dst, src);
        }
    };

    const int NIT = K / 32;
    fill(0, 0);
    asm volatile("cp.async.commit_group;");

    for (int it2 = 0; it2 < NIT; it2++) {
        asm volatile("cp.async.wait_group 0;");
        __syncthreads();
        if (it2 + 1 < NIT) {
            fill((it2 + 1) & 1, (it2 + 1) * 32);
            asm volatile("cp.async.commit_group;");
        }
        unsigned sb = smem_base + (unsigned)((it2 & 1) * G_STG * 2);

        unsigned ah[2][2][4], al[2][2][4];
#pragma unroll
        for (int mf = 0; mf < 2; mf++)
#pragma unroll
            for (int kk = 0; kk < 2; kk++) {
                unsigned base = (unsigned)(((wid * 32 + mf * 16) * GASTR + kk * 16) * 2);
                LDSM4(ah[mf][kk][0], ah[mf][kk][1], ah[mf][kk][2], ah[mf][kk][3],
                      sb + base + a_lofs);
                LDSM4(al[mf][kk][0], al[mf][kk][1], al[mf][kk][2], al[mf][kk][3],
                      sb + (unsigned)(G_AL * 2) + base + a_lofs);
            }

#pragma unroll
        for (int nf = 0; nf < 8; nf++) {
            unsigned wh[4], wl[4];
            unsigned wbase = (unsigned)((nf * 8 * GASTR) * 2);
            LDSM4(wh[0], wh[1], wh[2], wh[3], sb + (unsigned)(G_WH * 2) + wbase + w_lofs);
            LDSM4(wl[0], wl[1], wl[2], wl[3], sb + (unsigned)(G_WL * 2) + wbase + w_lofs);
#pragma unroll
            for (int mf = 0; mf < 2; mf++)
#pragma unroll
                for (int kk = 0; kk < 2; kk++) {
                    mma16816(o[mf][nf][0], o[mf][nf][1], o[mf][nf][2], o[mf][nf][3],
                             ah[mf][kk][0], ah[mf][kk][1], ah[mf][kk][2], ah[mf][kk][3],
                             wh[2 * kk], wh[2 * kk + 1]);
                    mma16816(o[mf][nf][0], o[mf][nf][1], o[mf][nf][2], o[mf][nf][3],
                             ah[mf][kk][0], ah[mf][kk][1], ah[mf][kk][2], ah[mf][kk][3],
                             wl[2 * kk], wl[2 * kk + 1]);
                    mma16816(o[mf][nf][0], o[mf][nf][1], o[mf][nf][2], o[mf][nf][3],
                             al[mf][kk][0], al[mf][kk][1], al[mf][kk][2], al[mf][kk][3],
                             wh[2 * kk], wh[2 * kk + 1]);
                }
        }
    }

    // epilogue: fp16 V row-major
#pragma unroll
    for (int mf = 0; mf < 2; mf++) {
        int row0 = m0 + wid * 32 + mf * 16 + grp;
        int row1 = row0 + 8;
#pragma unroll
        for (int nf = 0; nf < 8; nf++) {
            int col = n0 + nf * 8 + 2 * t;
            float b0 = bias[col], b1 = bias[col + 1];
            *(__half2*)(g_V + (size_t)row0 * DMODEL + col) =
                __floats2half2_rn(o[mf][nf][0] + b0, o[mf][nf][1] + b1);
            *(__half2*)(g_V + (size_t)row1 * DMODEL + col) =
                __floats2half2_rn(o[mf][nf][2] + b0, o[mf][nf][3] + b1);
        }
    }
}

// ---------------- fp16-MMA flash attention (BK=128 iters, exp2 softmax) ----------------
#define KSTR 40    // halves: 80 B row stride -> conflict-free LDSM
#define VSTR2 136  // halves: 272 B row stride ([k][n] tile) -> conflict-free trans LDSM

#define STG_V    (128 * KSTR)
#define STG_SIZE (128 * KSTR + 128 * VSTR2)   // 22528 halves = 45056 B
#define NSTAGE   2
#define NTILE    (SEQ / 128)                  // 32

__global__ void __launch_bounds__(128, 2)
attn_kernel(float* __restrict__ O)
{
    extern __shared__ __align__(16) __half sm[];

    const int tid  = threadIdx.x;
    const int wid  = tid >> 5;
    const int lane = tid & 31;
    const int grp  = lane >> 2;
    const int t    = lane & 3;
    const int h    = blockIdx.y;
    const int q0   = blockIdx.x * 64;
    const int qr   = q0 + wid * 16;

    const unsigned smem_base = (unsigned)__cvta_generic_to_shared(sm);

    const int mi = lane >> 3;
    const int r8 = lane & 7;
    const unsigned k_lofs = (unsigned)((r8 * KSTR + (mi >> 1) * 16 + (mi & 1) * 8) * 2);
    const unsigned v_lofs = (unsigned)(((((mi & 1) * 8 + r8) * VSTR2) + (mi >> 1) * 8) * 2);

    // ---- Q fragments (fp16, pre-scaled by log2(e) -> softmax uses bare exp2) ----
    const float L2E = 1.44269504088896341f;
    unsigned qh[2][4];
#pragma unroll
    for (int c = 0; c < 2; c++) {
        int cb = h * DH + 16 * c;
        const float* r0p = g_Q + (size_t)(qr + grp) * ZIPD + cb;
        const float* r1p = g_Q + (size_t)(qr + grp + 8) * ZIPD + cb;
        float2 xs[4];
        xs[0] = *(const float2*)(r0p + 2 * t);
        xs[1] = *(const float2*)(r1p + 2 * t);
        xs[2] = *(const float2*)(r0p + 8 + 2 * t);
        xs[3] = *(const float2*)(r1p + 8 + 2 * t);
#pragma unroll
        for (int i = 0; i < 4; i++)
            qh[c][i] = h2u(__floats2half2_rn(xs[i].x * L2E, xs[i].y * L2E));
    }

    float m0v = -1e30f, m1v = -1e30f, l0 = 0.f, l1 = 0.f;
    float o[16][4];
#pragma unroll
    for (int n = 0; n < 16; n++)
#pragma unroll
        for (int j = 0; j < 4; j++) o[n][j] = 0.f;

    auto fill = [&](int stage, int k0) {
        unsigned sbase = smem_base + (unsigned)(stage * STG_SIZE * 2);
        // K: 128 rows x 4 chunks = 512
#pragma unroll
        for (int it = 0; it < 4; it++) {
            int c   = it * 128 + tid;
            int key = c >> 2;
            int ch  = c & 3;
            const __half* src = g_Kh + (size_t)(k0 + key) * ZIPD + h * DH + ch * 8;
            unsigned dst = sbase + (unsigned)((key * KSTR + ch * 8) * 2);
            CP16(dst, src);
        }
        // V: 128 rows x 16 chunks = 2048
#pragma unroll
        for (int it = 0; it < 16; it++) {
            int c   = it * 128 + tid;
            int row = c >> 4;
            int col = c & 15;
            const __half* src = g_V + (size_t)(k0 + row) * DMODEL + h * DV + col * 8;
            unsigned dst = sbase + (unsigned)((STG_V + row * VSTR2 + col * 8) * 2);
            CP16(dst, src);
        }
    };

    fill(0, 0);
    asm volatile("cp.async.commit_group;");

    for (int kt = 0; kt < NTILE; kt++) {
        asm volatile("cp.async.wait_group 0;");
        __syncthreads();   // tile kt visible; other stage's reads (iter kt-1) fenced
        if (kt + 1 < NTILE) {
            fill((kt + 1) & 1, (kt + 1) * 128);
            asm volatile("cp.async.commit_group;");
        }

        const unsigned sb   = smem_base + (unsigned)((kt & 1) * STG_SIZE * 2);
        const unsigned sbKh = sb;
        const unsigned sbV  = sb + STG_V * 2;

        // ---- S = Q K^T over 128 keys (log2 domain) ----
        float sc[2][8][4];
#pragma unroll
        for (int s2 = 0; s2 < 2; s2++)
#pragma unroll
            for (int nb = 0; nb < 8; nb++)
#pragma unroll
                for (int j = 0; j < 4; j++) sc[s2][nb][j] = 0.f;

#pragma unroll
        for (int s2 = 0; s2 < 2; s2++)
#pragma unroll
            for (int nb = 0; nb < 8; nb++) {
                unsigned bh[4];
                LDSM4(bh[0], bh[1], bh[2], bh[3],
                      sbKh + (unsigned)(((s2 * 64 + nb * 8) * KSTR) * 2) + k_lofs);
#pragma unroll
                for (int c = 0; c < 2; c++)
                    mma16816(sc[s2][nb][0], sc[s2][nb][1], sc[s2][nb][2], sc[s2][nb][3],
                             qh[c][0], qh[c][1], qh[c][2], qh[c][3], bh[2 * c], bh[2 * c + 1]);
            }

        // ---- online softmax over 128 keys (exp2 domain) ----
        float mx0 = -1e30f, mx1 = -1e30f;
#pragma unroll
        for (int s2 = 0; s2 < 2; s2++)
#pragma unroll
            for (int nb = 0; nb < 8; nb++) {
                mx0 = fmaxf(mx0, fmaxf(sc[s2][nb][0], sc[s2][nb][1]));
                mx1 = fmaxf(mx1, fmaxf(sc[s2][nb][2], sc[s2][nb][3]));
            }
        mx0 = fmaxf(mx0, __shfl_xor_sync(0xffffffffu, mx0, 1));
        mx0 = fmaxf(mx0, __shfl_xor_sync(0xffffffffu, mx0, 2));
        mx1 = fmaxf(mx1, __shfl_xor_sync(0xffffffffu, mx1, 1));
        mx1 = fmaxf(mx1, __shfl_xor_sync(0xffffffffu, mx1, 2));

        float mn0 = fmaxf(m0v, mx0), mn1 = fmaxf(m1v, mx1);
        bool nochange = (mn0 == m0v) && (mn1 == m1v);
        bool skip = __all_sync(0xffffffffu, nochange);

        float s0 = 0.f, s1 = 0.f;
#pragma unroll
        for (int s2 = 0; s2 < 2; s2++)
#pragma unroll
            for (int nb = 0; nb < 8; nb++) {
                sc[s2][nb][0] = exp2f(sc[s2][nb][0] - mn0);
                sc[s2][nb][1] = exp2f(sc[s2][nb][1] - mn0);
                sc[s2][nb][2] = exp2f(sc[s2][nb][2] - mn1);
                sc[s2][nb][3] = exp2f(sc[s2][nb][3] - mn1);
                s0 += sc[s2][nb][0] + sc[s2][nb][1];
                s1 += sc[s2][nb][2] + sc[s2][nb][3];
            }
        s0 += __shfl_xor_sync(0xffffffffu, s0, 1);
        s0 += __shfl_xor_sync(0xffffffffu, s0, 2);
        s1 += __shfl_xor_sync(0xffffffffu, s1, 1);
        s1 += __shfl_xor_sync(0xffffffffu, s1, 2);

        if (skip) {
            l0 += s0;
            l1 += s1;
        } else {
            float e0 = exp2f(m0v - mn0), e1 = exp2f(m1v - mn1);
            m0v = mn0; m1v = mn1;
            l0 = l0 * e0 + s0;
            l1 = l1 * e1 + s1;
#pragma unroll
            for (int n = 0; n < 16; n++) {
                o[n][0] *= e0; o[n][1] *= e0;
                o[n][2] *= e1; o[n][3] *= e1;
            }
        }

        // ---- O += P V over 128 keys ----
#pragma unroll
        for (int s2 = 0; s2 < 2; s2++)
#pragma unroll
            for (int j = 0; j < 4; j++) {
                unsigned a0 = h2u(__floats2half2_rn(sc[s2][2 * j][0],     sc[s2][2 * j][1]));
                unsigned a1 = h2u(__floats2half2_rn(sc[s2][2 * j][2],     sc[s2][2 * j][3]));
                unsigned a2 = h2u(__floats2half2_rn(sc[s2][2 * j + 1][0], sc[s2][2 * j + 1][1]));
                unsigned a3 = h2u(__floats2half2_rn(sc[s2][2 * j + 1][2], sc[s2][2 * j + 1][3]));
#pragma unroll
                for (int p = 0; p < 8; p++) {
                    unsigned bv[4];
                    LDSM4T(bv[0], bv[1], bv[2], bv[3],
                           sbV + (unsigned)((((s2 * 64 + j * 16) * VSTR2) + p * 16) * 2) + v_lofs);
                    mma16816(o[2 * p][0], o[2 * p][1], o[2 * p][2], o[2 * p][3],
                             a0, a1, a2, a3, bv[0], bv[1]);
                    mma16816(o[2 * p + 1][0], o[2 * p + 1][1], o[2 * p + 1][2], o[2 * p + 1][3],
                             a0, a1, a2, a3, bv[2], bv[3]);
                }
            }
    }

    // ---- epilogue ----
    float inv0 = 1.f / l0, inv1 = 1.f / l1;
    int row0 = qr + grp, row1 = qr + grp + 8;
#pragma unroll
    for (int p = 0; p < 16; p++) {
        int col = h * DV + p * 8 + 2 * t;
        *(float2*)(O + (size_t)row0 * DMODEL + col) = make_float2(o[p][0] * inv0, o[p][1] * inv0);
        *(float2*)(O + (size_t)row1 * DMODEL + col) = make_float2(o[p][2] * inv1, o[p][3] * inv1);
    }
}

// ---------------- launch ----------------
extern "C" void kernel_launch(void* const* d_in, const int* in_sizes, int n_in,
                              void* d_out, int out_size)
{
    const float* q   = (const float*)d_in[0];
    const float* k   = (const float*)d_in[1];
    const float* v   = (const float*)d_in[2];
    const float* wq  = (const float*)d_in[3];
    const float* bq  = (const float*)d_in[4];
    const float* wk  = (const float*)d_in[5];
    const float* bk  = (const float*)d_in[6];
    const float* wvr = (const float*)d_in[7];
    const float* bvr = (const float*)d_in[8];
    const float* wvl = (const float*)d_in[9];
    const float* bvl = (const float*)d_in[10];
    float* out = (float*)d_out;

    conv_w_kernel<<<(4 * ZIPD * DMODEL / 4) / 256, 256>>>(wq, wk, wvr, wvl);

    const int GEMM_SMEM = 2 * G_STG * (int)sizeof(__half);   // 61440 B
    cudaFuncSetAttribute(gemm1_kernel, cudaFuncAttributeMaxDynamicSharedMemorySize, GEMM_SMEM);
    cudaFuncSetAttribute(gemm2_kernel, cudaFuncAttributeMaxDynamicSharedMemorySize, GEMM_SMEM);

    gemm1_kernel<<<dim3(ZIPD / 64, SEQ / 128, 3), 128, GEMM_SMEM>>>(q, k, v, bq, bk, bvr);
    gemm2_kernel<<<dim3(DMODEL / 64, SEQ / 128, 1), 128, GEMM_SMEM>>>(bvl);

    const int ATTN_SMEM = NSTAGE * STG_SIZE * (int)sizeof(__half);   // 90112 B
    cudaFuncSetAttribute(attn_kernel, cudaFuncAttributeMaxDynamicSharedMemorySize, ATTN_SMEM);
    attn_kernel<<<dim3(SEQ / 64, HEADS), 128, ATTN_SMEM>>>(out);
}

// round 12
// speedup vs baseline: 3.7515x; 1.1208x over previous
#include <cuda_runtime.h>
#include <cuda_fp16.h>
#include <math.h>

#define SEQ    4096
#define DMODEL 1024
#define HEADS  8
#define ZIPD   256
#define DH     32      // ZIP / HEADS
#define DV     128     // DMODEL / HEADS

// ---------------- scratch (no allocation allowed) ----------------
__device__ __align__(16) float  g_Q[SEQ * ZIPD];                 // 4 MB   fp32 Q-proj
__device__ __align__(16) __half g_Kh[SEQ * ZIPD];                // 2 MB   K-proj fp16
__device__ __align__(16) __half g_Th[SEQ * ZIPD];                // 2 MB   T (v@wvr) hi
__device__ __align__(16) __half g_Tl[SEQ * ZIPD];                // 2 MB   T lo
__device__ __align__(16) __half g_V[SEQ * DMODEL];               // 8 MB   value, fp16 row-major
__device__ __align__(16) __half g_Wh[3 * ZIPD * DMODEL];         // 1.5 MB wq,wk,wvr hi
__device__ __align__(16) __half g_Wl[3 * ZIPD * DMODEL];         // 1.5 MB lo
__device__ __align__(16) __half g_WVh[DMODEL * ZIPD];            // 0.5 MB wvl hi
__device__ __align__(16) __half g_WVl[DMODEL * ZIPD];            // 0.5 MB lo
__device__ int g_KmaxI[HEADS];                                   // max ||k||^2 per head (float bits; idempotent)

__device__ __forceinline__ unsigned h2u(__half2 h) { return *reinterpret_cast<unsigned*>(&h); }

__device__ __forceinline__ float ex2(float x)
{
    float y;
    asm("ex2.approx.ftz.f32 %0, %1;" : "=f"(y) : "f"(x));
    return y;
}

// split float4 -> hi half4 + lo half4
__device__ __forceinline__ void split4(float4 v, uint2& uh, uint2& ul)
{
    __half h0 = __float2half_rn(v.x), h1 = __float2half_rn(v.y);
    __half h2 = __float2half_rn(v.z), h3 = __float2half_rn(v.w);
    uh.x = h2u(__halves2half2(h0, h1));
    uh.y = h2u(__halves2half2(h2, h3));
    ul.x = h2u(__floats2half2_rn(v.x - __half2float(h0), v.y - __half2float(h1)));
    ul.y = h2u(__floats2half2_rn(v.z - __half2float(h2), v.w - __half2float(h3)));
}

// ---------------- weight conversion ----------------
__global__ void conv_w_kernel(const float* __restrict__ wq,
                              const float* __restrict__ wk,
                              const float* __restrict__ wvr,
                              const float* __restrict__ wvl)
{
    int i = blockIdx.x * 256 + threadIdx.x;              // float4 index
    const int WSZ = ZIPD * DMODEL / 4;                   // 65536
    uint2 uh, ul;
    if (i < 3 * WSZ) {
        int m = i / WSZ, off = i % WSZ;
        const float* src = (m == 0) ? wq : (m == 1) ? wk : wvr;
        float4 x = ((const float4*)src)[off];
        split4(x, uh, ul);
        ((uint2*)g_Wh)[i] = uh;
        ((uint2*)g_Wl)[i] = ul;
    } else {
        int off = i - 3 * WSZ;
        float4 x = ((const float4*)wvl)[off];
        split4(x, uh, ul);
        ((uint2*)g_WVh)[off] = uh;
        ((uint2*)g_WVl)[off] = ul;
    }
}

// ---------------- k-norm max kernel ----------------
// max over keys of ||k||^2 per head, from the SAME fp16 data attention's MMA reads.
// atomicMax on positive-float bits is order-preserving and idempotent across graph replays.
__global__ void knorm_kernel()
{
    __shared__ float red[256];
    const int h   = blockIdx.y;
    const int key = blockIdx.x * 256 + threadIdx.x;
    const uint4* kp = (const uint4*)(g_Kh + (size_t)key * ZIPD + h * DH);
    float s = 0.f;
#pragma unroll
    for (int i = 0; i < 4; i++) {
        uint4 u = kp[i];
        unsigned w[4] = {u.x, u.y, u.z, u.w};
#pragma unroll
        for (int j = 0; j < 4; j++) {
            __half2 hv = *reinterpret_cast<__half2*>(&w[j]);
            float2 f = __half22float2(hv);
            s = fmaf(f.x, f.x, s);
            s = fmaf(f.y, f.y, s);
        }
    }
    red[threadIdx.x] = s;
    __syncthreads();
#pragma unroll
    for (int st = 128; st > 0; st >>= 1) {
        if (threadIdx.x < st) red[threadIdx.x] = fmaxf(red[threadIdx.x], red[threadIdx.x + st]);
        __syncthreads();
    }
    if (threadIdx.x == 0)
        atomicMax(&g_KmaxI[h], __float_as_int(red[0]));
}

// ---------------- MMA helpers ----------------
__device__ __forceinline__ void mma16816(float& c0, float& c1, float& c2, float& c3,
                                         unsigned a0, unsigned a1, unsigned a2, unsigned a3,
                                         unsigned b0, unsigned b1)
{
    asm volatile("mma.sync.aligned.m16n8k16.row.col.f32.f16.f16.f32 "
                 "{%0,%1,%2,%3},{%4,%5,%6,%7},{%8,%9},{%0,%1,%2,%3};"
                 : "+f"(c0), "+f"(c1), "+f"(c2), "+f"(c3)
                 : "r"(a0), "r"(a1), "r"(a2), "r"(a3), "r"(b0), "r"(b1));
}

#define LDSM4(R0, R1, R2, R3, ADDR) \
    asm volatile("ldmatrix.sync.aligned.m8n8.x4.shared.b16 {%0,%1,%2,%3}, [%4];" \
                 : "=r"(R0), "=r"(R1), "=r"(R2), "=r"(R3) : "r"(ADDR))

#define LDSM4T(R0, R1, R2, R3, ADDR) \
    asm volatile("ldmatrix.sync.aligned.m8n8.x4.trans.shared.b16 {%0,%1,%2,%3}, [%4];" \
                 : "=r"(R0), "=r"(R1), "=r"(R2), "=r"(R3) : "r"(ADDR))

#define CP16(DST, SRC) \
    asm volatile("cp.async.cg.shared.global [%0], [%1], 16;" :: "r"(DST), "l"(SRC))

// ---------------- GEMM smem layout ----------------
#define GASTR 40
#define G_AL  (128 * GASTR)
#define G_WH  (2 * 128 * GASTR)
#define G_WL  (2 * 128 * GASTR + 64 * GASTR)
#define G_STG (2 * 128 * GASTR + 2 * 64 * GASTR)   // 15360 halves = 30720 B

// ---------------- gemm1: fused fp32->hi/lo split + MMA ----------------
// mode: 0 -> g_Q fp32; 1 -> g_Kh fp16; 2 -> g_Th/g_Tl
__global__ void __launch_bounds__(128, 3)
gemm1_kernel(const float* __restrict__ qin, const float* __restrict__ kin,
             const float* __restrict__ vin,
             const float* __restrict__ bq, const float* __restrict__ bk,
             const float* __restrict__ bvr)
{
    extern __shared__ __align__(16) __half gsm[];
    const unsigned smem_base = (unsigned)__cvta_generic_to_shared(gsm);

    const int mode = blockIdx.z;
    const float* A    = (mode == 0) ? qin : (mode == 1) ? kin : vin;
    const __half* Wh  = g_Wh + (size_t)mode * ZIPD * DMODEL;
    const __half* Wl  = g_Wl + (size_t)mode * ZIPD * DMODEL;
    const float* bias = (mode == 0) ? bq : (mode == 1) ? bk : bvr;
    const int K = DMODEL;

    const int tid  = threadIdx.x;
    const int wid  = tid >> 5;
    const int lane = tid & 31;
    const int grp  = lane >> 2;
    const int t    = lane & 3;
    const int mi   = lane >> 3;
    const int r8   = lane & 7;
    const int m0   = blockIdx.y * 128;
    const int n0   = blockIdx.x * 64;

    const unsigned a_lofs = (unsigned)(((((mi & 1) * 8 + r8) * GASTR) + (mi >> 1) * 8) * 2);
    const unsigned w_lofs = (unsigned)((r8 * GASTR + (mi >> 1) * 16 + (mi & 1) * 8) * 2);

    float o[2][8][4];
#pragma unroll
    for (int mf = 0; mf < 2; mf++)
#pragma unroll
        for (int nf = 0; nf < 8; nf++)
#pragma unroll
            for (int r = 0; r < 4; r++) o[mf][nf][r] = 0.f;

    float4 areg[8];
    auto ldA = [&](int k0) {
#pragma unroll
        for (int it = 0; it < 8; it++) {
            int c = it * 128 + tid;
            int row = c >> 3, ch = c & 7;
            areg[it] = *(const float4*)(A + (size_t)(m0 + row) * K + k0 + ch * 4);
        }
    };
    auto stsA = [&](int stage) {
#pragma unroll
        for (int it = 0; it < 8; it++) {
            int c = it * 128 + tid;
            int row = c >> 3, ch = c & 7;
            uint2 uh, ul;
            split4(areg[it], uh, ul);
            *(uint2*)(gsm + stage * G_STG + row * GASTR + ch * 4) = uh;
            *(uint2*)(gsm + stage * G_STG + G_AL + row * GASTR + ch * 4) = ul;
        }
    };
    auto fillW = [&](int stage, int k0) {
#pragma unroll
        for (int it = 0; it < 4; it++) {
            int c = it * 128 + tid;
            int arr = c >> 8, cc = c & 255;
            int row = cc >> 2, ch = cc & 3;
            const __half* src = (arr ? Wl : Wh) + (size_t)(n0 + row) * K + k0 + ch * 8;
            unsigned dst = smem_base +
                (unsigned)((stage * G_STG + (arr ? G_WL : G_WH) + row * GASTR + ch * 8) * 2);
            CP16(dst, src);
        }
    };

    const int NIT = K / 32;   // 32
    ldA(0);
    stsA(0);
    fillW(0, 0);
    asm volatile("cp.async.commit_group;");
    ldA(32);

    for (int it2 = 0; it2 < NIT; it2++) {
        asm volatile("cp.async.wait_group 0;");
        __syncthreads();
        if (it2 + 1 < NIT) {
            stsA((it2 + 1) & 1);
            fillW((it2 + 1) & 1, (it2 + 1) * 32);
            asm volatile("cp.async.commit_group;");
            if (it2 + 2 < NIT) ldA((it2 + 2) * 32);
        }
        unsigned sb = smem_base + (unsigned)((it2 & 1) * G_STG * 2);

        unsigned ah[2][2][4], al[2][2][4];
#pragma unroll
        for (int mf = 0; mf < 2; mf++)
#pragma unroll
            for (int kk = 0; kk < 2; kk++) {
                unsigned base = (unsigned)(((wid * 32 + mf * 16) * GASTR + kk * 16) * 2);
                LDSM4(ah[mf][kk][0], ah[mf][kk][1], ah[mf][kk][2], ah[mf][kk][3],
                      sb + base + a_lofs);
                LDSM4(al[mf][kk][0], al[mf][kk][1], al[mf][kk][2], al[mf][kk][3],
                      sb + (unsigned)(G_AL * 2) + base + a_lofs);
            }

#pragma unroll
        for (int nf = 0; nf < 8; nf++) {
            unsigned wh[4], wl[4];
            unsigned wbase = (unsigned)((nf * 8 * GASTR) * 2);
            LDSM4(wh[0], wh[1], wh[2], wh[3], sb + (unsigned)(G_WH * 2) + wbase + w_lofs);
            LDSM4(wl[0], wl[1], wl[2], wl[3], sb + (unsigned)(G_WL * 2) + wbase + w_lofs);
#pragma unroll
            for (int mf = 0; mf < 2; mf++)
#pragma unroll
                for (int kk = 0; kk < 2; kk++) {
                    mma16816(o[mf][nf][0], o[mf][nf][1], o[mf][nf][2], o[mf][nf][3],
                             ah[mf][kk][0], ah[mf][kk][1], ah[mf][kk][2], ah[mf][kk][3],
                             wh[2 * kk], wh[2 * kk + 1]);
                    mma16816(o[mf][nf][0], o[mf][nf][1], o[mf][nf][2], o[mf][nf][3],
                             ah[mf][kk][0], ah[mf][kk][1], ah[mf][kk][2], ah[mf][kk][3],
                             wl[2 * kk], wl[2 * kk + 1]);
                    mma16816(o[mf][nf][0], o[mf][nf][1], o[mf][nf][2], o[mf][nf][3],
                             al[mf][kk][0], al[mf][kk][1], al[mf][kk][2], al[mf][kk][3],
                             wh[2 * kk], wh[2 * kk + 1]);
                }
        }
    }

    // ---- epilogue ----
#pragma unroll
    for (int mf = 0; mf < 2; mf++) {
        int row0 = m0 + wid * 32 + mf * 16 + grp;
        int row1 = row0 + 8;
#pragma unroll
        for (int nf = 0; nf < 8; nf++) {
            int col = n0 + nf * 8 + 2 * t;
            float b0 = bias[col], b1 = bias[col + 1];
            float x0 = o[mf][nf][0] + b0, x1 = o[mf][nf][1] + b1;
            float x2 = o[mf][nf][2] + b0, x3 = o[mf][nf][3] + b1;
            if (mode == 0) {
                *(float2*)(g_Q + (size_t)row0 * ZIPD + col) = make_float2(x0, x1);
                *(float2*)(g_Q + (size_t)row1 * ZIPD + col) = make_float2(x2, x3);
            } else if (mode == 1) {
                *(__half2*)(g_Kh + (size_t)row0 * ZIPD + col) = __floats2half2_rn(x0, x1);
                *(__half2*)(g_Kh + (size_t)row1 * ZIPD + col) = __floats2half2_rn(x2, x3);
            } else {
                __half h0 = __float2half_rn(x0), h1 = __float2half_rn(x1);
                __half h2 = __float2half_rn(x2), h3 = __float2half_rn(x3);
                *(__half2*)(g_Th + (size_t)row0 * ZIPD + col) = __halves2half2(h0, h1);
                *(__half2*)(g_Th + (size_t)row1 * ZIPD + col) = __halves2half2(h2, h3);
                *(__half2*)(g_Tl + (size_t)row0 * ZIPD + col) =
                    __floats2half2_rn(x0 - __half2float(h0), x1 - __half2float(h1));
                *(__half2*)(g_Tl + (size_t)row1 * ZIPD + col) =
                    __floats2half2_rn(x2 - __half2float(h2), x3 - __half2float(h3));
            }
        }
    }
}

// ---------------- gemm2: T @ wvl^T ----------------
__global__ void __launch_bounds__(128, 2)
gemm2_kernel(const float* __restrict__ bvl)
{
    extern __shared__ __align__(16) __half gsm[];
    const unsigned smem_base = (unsigned)__cvta_generic_to_shared(gsm);

    const __half* Ah = g_Th;
    const __half* Al = g_Tl;
    const __half* Wh = g_WVh;
    const __half* Wl = g_WVl;
    const float* bias = bvl;
    const int K = ZIPD;

    const int tid  = threadIdx.x;
    const int wid  = tid >> 5;
    const int lane = tid & 31;
    const int grp  = lane >> 2;
    const int t    = lane & 3;
    const int mi   = lane >> 3;
    const int r8   = lane & 7;
    const int m0   = blockIdx.y * 128;
    const int n0   = blockIdx.x * 64;

    const unsigned a_lofs = (unsigned)(((((mi & 1) * 8 + r8) * GASTR) + (mi >> 1) * 8) * 2);
    const unsigned w_lofs = (unsigned)((r8 * GASTR + (mi >> 1) * 16 + (mi & 1) * 8) * 2);

    float o[2][8][4];
#pragma unroll
    for (int mf = 0; mf < 2; mf++)
#pragma unroll
        for (int nf = 0; nf < 8; nf++)
#pragma unroll
            for (int r = 0; r < 4; r++) o[mf][nf][r] = 0.f;

    auto fill = [&](int stage, int k0) {
        unsigned sb = smem_base + (unsigned)(stage * G_STG * 2);
#pragma unroll
        for (int it = 0; it < 8; it++) {
            int c = it * 128 + tid;
            int arr = c >> 9, cc = c & 511;
            int row = cc >> 2, ch = cc & 3;
            const __half* src = (arr ? Al : Ah) + (size_t)(m0 + row) * K + k0 + ch * 8;
            unsigned dst = sb + (unsigned)(((arr ? G_AL : 0) + row * GASTR + ch * 8) * 2);
            CP16(dst, src);
        }
#pragma unroll
        for (int it = 0; it < 4; it++) {
            int c = it * 128 + tid;
            int arr = c >> 8, cc = c & 255;
            int row = cc >> 2, ch = cc & 3;
            const __half* src = (arr ? Wl : Wh) + (size_t)(n0 + row) * K + k0 + ch * 8;
            unsigned dst = sb + (unsigned)(((arr ? G_WL : G_WH) + row * GASTR + ch * 8) * 2);
            CP16(dst, src);
        }
    };

    const int NIT = K / 32;
    fill(0, 0);
    asm volatile("cp.async.commit_group;");

    for (int it2 = 0; it2 < NIT; it2++) {
        asm volatile("cp.async.wait_group 0;");
        __syncthreads();
        if (it2 + 1 < NIT) {
            fill((it2 + 1) & 1, (it2 + 1) * 32);
            asm volatile("cp.async.commit_group;");
        }
        unsigned sb = smem_base + (unsigned)((it2 & 1) * G_STG * 2);

        unsigned ah[2][2][4], al[2][2][4];
#pragma unroll
        for (int mf = 0; mf < 2; mf++)
#pragma unroll
            for (int kk = 0; kk < 2; kk++) {
                unsigned base = (unsigned)(((wid * 32 + mf * 16) * GASTR + kk * 16) * 2);
                LDSM4(ah[mf][kk][0], ah[mf][kk][1], ah[mf][kk][2], ah[mf][kk][3],
                      sb + base + a_lofs);
                LDSM4(al[mf][kk][0], al[mf][kk][1], al[mf][kk][2], al[mf][kk][3],
                      sb + (unsigned)(G_AL * 2) + base + a_lofs);
            }

#pragma unroll
        for (int nf = 0; nf < 8; nf++) {
            unsigned wh[4], wl[4];
            unsigned wbase = (unsigned)((nf * 8 * GASTR) * 2);
            LDSM4(wh[0], wh[1], wh[2], wh[3], sb + (unsigned)(G_WH * 2) + wbase + w_lofs);
            LDSM4(wl[0], wl[1], wl[2], wl[3], sb + (unsigned)(G_WL * 2) + wbase + w_lofs);
#pragma unroll
            for (int mf = 0; mf < 2; mf++)
#pragma unroll
                for (int kk = 0; kk < 2; kk++) {
                    mma16816(o[mf][nf][0], o[mf][nf][1], o[mf][nf][2], o[mf][nf][3],
                             ah[mf][kk][0], ah[mf][kk][1], ah[mf][kk][2], ah[mf][kk][3],
                             wh[2 * kk], wh[2 * kk + 1]);
                    mma16816(o[mf][nf][0], o[mf][nf][1], o[mf][nf][2], o[mf][nf][3],
                             ah[mf][kk][0], ah[mf][kk][1], ah[mf][kk][2], ah[mf][kk][3],
                             wl[2 * kk], wl[2 * kk + 1]);
                    mma16816(o[mf][nf][0], o[mf][nf][1], o[mf][nf][2], o[mf][nf][3],
                             al[mf][kk][0], al[mf][kk][1], al[mf][kk][2], al[mf][kk][3],
                             wh[2 * kk], wh[2 * kk + 1]);
                }
        }
    }

    // epilogue: fp16 V row-major
#pragma unroll
    for (int mf = 0; mf < 2; mf++) {
        int row0 = m0 + wid * 32 + mf * 16 + grp;
        int row1 = row0 + 8;
#pragma unroll
        for (int nf = 0; nf < 8; nf++) {
            int col = n0 + nf * 8 + 2 * t;
            float b0 = bias[col], b1 = bias[col + 1];
            *(__half2*)(g_V + (size_t)row0 * DMODEL + col) =
                __floats2half2_rn(o[mf][nf][0] + b0, o[mf][nf][1] + b1);
            *(__half2*)(g_V + (size_t)row1 * DMODEL + col) =
                __floats2half2_rn(o[mf][nf][2] + b0, o[mf][nf][3] + b1);
        }
    }
}

// ---------------- fp16-MMA flash attention (static-bound softmax, no online max) ----------------
#define KSTR 40    // halves: 80 B row stride -> conflict-free LDSM
#define VSTR2 136  // halves: 272 B row stride ([k][n] tile) -> conflict-free trans LDSM

#define STG_V    (128 * KSTR)
#define STG_SIZE (128 * KSTR + 128 * VSTR2)   // 22528 halves = 45056 B
#define NSTAGE   2
#define NTILE    (SEQ / 128)                  // 32

__global__ void __launch_bounds__(128, 2)
attn_kernel(float* __restrict__ O)
{
    extern __shared__ __align__(16) __half sm[];

    const int tid  = threadIdx.x;
    const int wid  = tid >> 5;
    const int lane = tid & 31;
    const int grp  = lane >> 2;
    const int t    = lane & 3;
    const int h    = blockIdx.y;
    const int q0   = blockIdx.x * 64;
    const int qr   = q0 + wid * 16;

    const unsigned smem_base = (unsigned)__cvta_generic_to_shared(sm);

    const int mi = lane >> 3;
    const int r8 = lane & 7;
    const unsigned k_lofs = (unsigned)((r8 * KSTR + (mi >> 1) * 16 + (mi & 1) * 8) * 2);
    const unsigned v_lofs = (unsigned)(((((mi & 1) * 8 + r8) * VSTR2) + (mi >> 1) * 8) * 2);

    // ---- Q fragments (fp16, pre-scaled by log2(e)), plus per-row ||q||^2 ----
    const float L2E = 1.44269504088896341f;
    unsigned qh[2][4];
    float qs0 = 0.f, qs1 = 0.f;   // ||q||^2 partial for rows grp / grp+8
#pragma unroll
    for (int c = 0; c < 2; c++) {
        int cb = h * DH + 16 * c;
        const float* r0p = g_Q + (size_t)(qr + grp) * ZIPD + cb;
        const float* r1p = g_Q + (size_t)(qr + grp + 8) * ZIPD + cb;
        float2 xs[4];
        xs[0] = *(const float2*)(r0p + 2 * t);
        xs[1] = *(const float2*)(r1p + 2 * t);
        xs[2] = *(const float2*)(r0p + 8 + 2 * t);
        xs[3] = *(const float2*)(r1p + 8 + 2 * t);
        qs0 = fmaf(xs[0].x, xs[0].x, qs0); qs0 = fmaf(xs[0].y, xs[0].y, qs0);
        qs0 = fmaf(xs[2].x, xs[2].x, qs0); qs0 = fmaf(xs[2].y, xs[2].y, qs0);
        qs1 = fmaf(xs[1].x, xs[1].x, qs1); qs1 = fmaf(xs[1].y, xs[1].y, qs1);
        qs1 = fmaf(xs[3].x, xs[3].x, qs1); qs1 = fmaf(xs[3].y, xs[3].y, qs1);
#pragma unroll
        for (int i = 0; i < 4; i++)
            qh[c][i] = h2u(__floats2half2_rn(xs[i].x * L2E, xs[i].y * L2E));
    }
    // reduce ||q||^2 over the 4 lanes of the quad (lanes grp*4+t)
    qs0 += __shfl_xor_sync(0xffffffffu, qs0, 1);
    qs0 += __shfl_xor_sync(0xffffffffu, qs0, 2);
    qs1 += __shfl_xor_sync(0xffffffffu, qs1, 1);
    qs1 += __shfl_xor_sync(0xffffffffu, qs1, 2);

    // static per-row bound (log2 domain): m = l2e*||q||*||k||max - 15
    // guarantees s_log2 - m <= 15 + tiny rounding slack -> p <= 2^15.02 < fp16 max
    const float kmax2 = __int_as_float(g_KmaxI[h]);   // max ||k||^2 over this head's keys
    const float m0c = sqrtf(qs0 * kmax2) * L2E - 15.0f;
    const float m1c = sqrtf(qs1 * kmax2) * L2E - 15.0f;

    float l0 = 0.f, l1 = 0.f;
    float o[16][4];
#pragma unroll
    for (int n = 0; n < 16; n++)
#pragma unroll
        for (int j = 0; j < 4; j++) o[n][j] = 0.f;

    auto fill = [&](int stage, int k0) {
        unsigned sbase = smem_base + (unsigned)(stage * STG_SIZE * 2);
#pragma unroll
        for (int it = 0; it < 4; it++) {
            int c   = it * 128 + tid;
            int key = c >> 2;
            int ch  = c & 3;
            const __half* src = g_Kh + (size_t)(k0 + key) * ZIPD + h * DH + ch * 8;
            unsigned dst = sbase + (unsigned)((key * KSTR + ch * 8) * 2);
            CP16(dst, src);
        }
#pragma unroll
        for (int it = 0; it < 16; it++) {
            int c   = it * 128 + tid;
            int row = c >> 4;
            int col = c & 15;
            const __half* src = g_V + (size_t)(k0 + row) * DMODEL + h * DV + col * 8;
            unsigned dst = sbase + (unsigned)((STG_V + row * VSTR2 + col * 8) * 2);
            CP16(dst, src);
        }
    };

    fill(0, 0);
    asm volatile("cp.async.commit_group;");

    for (int kt = 0; kt < NTILE; kt++) {
        asm volatile("cp.async.wait_group 0;");
        __syncthreads();
        if (kt + 1 < NTILE) {
            fill((kt + 1) & 1, (kt + 1) * 128);
            asm volatile("cp.async.commit_group;");
        }

        const unsigned sb   = smem_base + (unsigned)((kt & 1) * STG_SIZE * 2);
        const unsigned sbKh = sb;
        const unsigned sbV  = sb + STG_V * 2;

        // ---- S = Q K^T over 128 keys (log2 domain) ----
        float sc[2][8][4];
#pragma unroll
        for (int s2 = 0; s2 < 2; s2++)
#pragma unroll
            for (int nb = 0; nb < 8; nb++)
#pragma unroll
                for (int j = 0; j < 4; j++) sc[s2][nb][j] = 0.f;

#pragma unroll
        for (int s2 = 0; s2 < 2; s2++)
#pragma unroll
            for (int nb = 0; nb < 8; nb++) {
                unsigned bh[4];
                LDSM4(bh[0], bh[1], bh[2], bh[3],
                      sbKh + (unsigned)(((s2 * 64 + nb * 8) * KSTR) * 2) + k_lofs);
#pragma unroll
                for (int c = 0; c < 2; c++)
                    mma16816(sc[s2][nb][0], sc[s2][nb][1], sc[s2][nb][2], sc[s2][nb][3],
                             qh[c][0], qh[c][1], qh[c][2], qh[c][3], bh[2 * c], bh[2 * c + 1]);
            }

        // ---- p = 2^(s - m), constant per-row m: no max pass, no shuffles, no rescale ----
#pragma unroll
        for (int s2 = 0; s2 < 2; s2++)
#pragma unroll
            for (int nb = 0; nb < 8; nb++) {
                sc[s2][nb][0] = ex2(sc[s2][nb][0] - m0c);
                sc[s2][nb][1] = ex2(sc[s2][nb][1] - m0c);
                sc[s2][nb][2] = ex2(sc[s2][nb][2] - m1c);
                sc[s2][nb][3] = ex2(sc[s2][nb][3] - m1c);
                l0 += sc[s2][nb][0] + sc[s2][nb][1];
                l1 += sc[s2][nb][2] + sc[s2][nb][3];
            }

        // ---- O += P V over 128 keys ----
#pragma unroll
        for (int s2 = 0; s2 < 2; s2++)
#pragma unroll
            for (int j = 0; j < 4; j++) {
                unsigned a0 = h2u(__floats2half2_rn(sc[s2][2 * j][0],     sc[s2][2 * j][1]));
                unsigned a1 = h2u(__floats2half2_rn(sc[s2][2 * j][2],     sc[s2][2 * j][3]));
                unsigned a2 = h2u(__floats2half2_rn(sc[s2][2 * j + 1][0], sc[s2][2 * j + 1][1]));
                unsigned a3 = h2u(__floats2half2_rn(sc[s2][2 * j + 1][2], sc[s2][2 * j + 1][3]));
#pragma unroll
                for (int p = 0; p < 8; p++) {
                    unsigned bv[4];
                    LDSM4T(bv[0], bv[1], bv[2], bv[3],
                           sbV + (unsigned)((((s2 * 64 + j * 16) * VSTR2) + p * 16) * 2) + v_lofs);
                    mma16816(o[2 * p][0], o[2 * p][1], o[2 * p][2], o[2 * p][3],
                             a0, a1, a2, a3, bv[0], bv[1]);
                    mma16816(o[2 * p + 1][0], o[2 * p + 1][1], o[2 * p + 1][2], o[2 * p + 1][3],
                             a0, a1, a2, a3, bv[2], bv[3]);
                }
            }
    }

    // ---- epilogue: single l reduction ----
    l0 += __shfl_xor_sync(0xffffffffu, l0, 1);
    l0 += __shfl_xor_sync(0xffffffffu, l0, 2);
    l1 += __shfl_xor_sync(0xffffffffu, l1, 1);
    l1 += __shfl_xor_sync(0xffffffffu, l1, 2);
    float inv0 = 1.f / l0, inv1 = 1.f / l1;
    int row0 = qr + grp, row1 = qr + grp + 8;
#pragma unroll
    for (int p = 0; p < 16; p++) {
        int col = h * DV + p * 8 + 2 * t;
        *(float2*)(O + (size_t)row0 * DMODEL + col) = make_float2(o[p][0] * inv0, o[p][1] * inv0);
        *(float2*)(O + (size_t)row1 * DMODEL + col) = make_float2(o[p][2] * inv1, o[p][3] * inv1);
    }
}

// ---------------- launch ----------------
extern "C" void kernel_launch(void* const* d_in, const int* in_sizes, int n_in,
                              void* d_out, int out_size)
{
    const float* q   = (const float*)d_in[0];
    const float* k   = (const float*)d_in[1];
    const float* v   = (const float*)d_in[2];
    const float* wq  = (const float*)d_in[3];
    const float* bq  = (const float*)d_in[4];
    const float* wk  = (const float*)d_in[5];
    const float* bk  = (const float*)d_in[6];
    const float* wvr = (const float*)d_in[7];
    const float* bvr = (const float*)d_in[8];
    const float* wvl = (const float*)d_in[9];
    const float* bvl = (const float*)d_in[10];
    float* out = (float*)d_out;

    conv_w_kernel<<<(4 * ZIPD * DMODEL / 4) / 256, 256>>>(wq, wk, wvr, wvl);

    const int GEMM_SMEM = 2 * G_STG * (int)sizeof(__half);   // 61440 B
    cudaFuncSetAttribute(gemm1_kernel, cudaFuncAttributeMaxDynamicSharedMemorySize, GEMM_SMEM);
    cudaFuncSetAttribute(gemm2_kernel, cudaFuncAttributeMaxDynamicSharedMemorySize, GEMM_SMEM);

    gemm1_kernel<<<dim3(ZIPD / 64, SEQ / 128, 3), 128, GEMM_SMEM>>>(q, k, v, bq, bk, bvr);

    knorm_kernel<<<dim3(SEQ / 256, HEADS), 256>>>();   // needs g_Kh (gemm1); idempotent atomicMax

    gemm2_kernel<<<dim3(DMODEL / 64, SEQ / 128, 1), 128, GEMM_SMEM>>>(bvl);

    const int ATTN_SMEM = NSTAGE * STG_SIZE * (int)sizeof(__half);   // 90112 B
    cudaFuncSetAttribute(attn_kernel, cudaFuncAttributeMaxDynamicSharedMemorySize, ATTN_SMEM);
    attn_kernel<<<dim3(SEQ / 64, HEADS), 128, ATTN_SMEM>>>(out);
}